// round 9
// baseline (speedup 1.0000x reference)
#include <cuda_runtime.h>
#include <math.h>
#include <cstdint>

#define D_MODEL 1024
#define N_HEADS 16
#define HD      64
#define BATCH   2
#define SEQ     2048
#define ROWS    (BATCH*SEQ)      // 4096
#define QKV_N   (3*D_MODEL)      // 3072
#define LN_EPS  1e-6f

// Scratch (device-global: no runtime allocation allowed)
__device__ float g_qkv[(size_t)ROWS * QKV_N];          // 48 MB fp32 qkv
__device__ float g_xhi[(size_t)ROWS * D_MODEL];        // x split
__device__ float g_xlo[(size_t)ROWS * D_MODEL];
__device__ float g_wqkv_hi[(size_t)D_MODEL * QKV_N];   // W_qkv split
__device__ float g_wqkv_lo[(size_t)D_MODEL * QKV_N];
__device__ float g_wout_hi[(size_t)D_MODEL * D_MODEL]; // W_out split
__device__ float g_wout_lo[(size_t)D_MODEL * D_MODEL];
__device__ float g_ctx_hi[(size_t)ROWS * D_MODEL];     // attention output split
__device__ float g_ctx_lo[(size_t)ROWS * D_MODEL];

__device__ __forceinline__ uint32_t smem_u32(const void* p) {
    return (uint32_t)__cvta_generic_to_shared(p);
}

__device__ __forceinline__ void mma_tf32(float* d, const uint32_t* a, const uint32_t* b) {
    asm volatile(
        "mma.sync.aligned.m16n8k8.row.col.f32.tf32.tf32.f32 "
        "{%0,%1,%2,%3}, {%4,%5,%6,%7}, {%8,%9}, {%0,%1,%2,%3};\n"
        : "+f"(d[0]), "+f"(d[1]), "+f"(d[2]), "+f"(d[3])
        : "r"(a[0]), "r"(a[1]), "r"(a[2]), "r"(a[3]), "r"(b[0]), "r"(b[1]));
}

// fp32 -> (tf32 hi, tf32 lo) with lo = rna_tf32(x - hi)
__device__ __forceinline__ void split_tf32(float x, uint32_t& hi, uint32_t& lo) {
    uint32_t h;
    asm("cvt.rna.tf32.f32 %0, %1;\n" : "=r"(h) : "f"(x));
    float resid = x - __uint_as_float(h);
    uint32_t l;
    asm("cvt.rna.tf32.f32 %0, %1;\n" : "=r"(l) : "f"(resid));
    hi = h; lo = l;
}

// ---------------------------------------------------------------------------
// Elementwise hi/lo split: src fp32 -> hi, lo (tf32-valued fp32). float4 I/O.
// n must be divisible by 4.
// ---------------------------------------------------------------------------
__global__ __launch_bounds__(256)
void split_kernel(const float* __restrict__ src, float* __restrict__ hi,
                  float* __restrict__ lo, int n4) {
    int i = blockIdx.x * blockDim.x + threadIdx.x;
    if (i >= n4) return;
    float4 v = ((const float4*)src)[i];
    uint32_t h0, l0, h1, l1, h2, l2, h3, l3;
    split_tf32(v.x, h0, l0);
    split_tf32(v.y, h1, l1);
    split_tf32(v.z, h2, l2);
    split_tf32(v.w, h3, l3);
    ((float4*)hi)[i] = make_float4(__uint_as_float(h0), __uint_as_float(h1),
                                   __uint_as_float(h2), __uint_as_float(h3));
    ((float4*)lo)[i] = make_float4(__uint_as_float(l0), __uint_as_float(l1),
                                   __uint_as_float(l2), __uint_as_float(l3));
}

// ===========================================================================
// 3xTF32 GEMM on PRE-SPLIT operands: C = A @ B, A=(Ahi,Alo), B=(Bhi,Blo).
// 128x128 CTA tile, BK=16, 256 threads = 8 warps (2m x 4n), warp tile 64x32.
// Inner loop: pure LDS + MMA (no cvt). Dynamic smem 75776 B.
// ===========================================================================
#define BM 128
#define BN 128
#define BK 16
#define AS_STRIDE 20
#define BS_STRIDE 136
// float offsets in dynamic smem
#define OFF_AH 0
#define OFF_AL (2*BM*AS_STRIDE)                 // 5120
#define OFF_BH (4*BM*AS_STRIDE)                 // 10240
#define OFF_BL (4*BM*AS_STRIDE + 2*BK*BS_STRIDE) // 14592
#define GEMM_SMEM_FLOATS (4*BM*AS_STRIDE + 4*BK*BS_STRIDE) // 18944 -> 75776 B

__global__ __launch_bounds__(256)
void gemm_tf32x3_pre_kernel(const float* __restrict__ Ahi, const float* __restrict__ Alo,
                            const float* __restrict__ Bhi, const float* __restrict__ Blo,
                            float* __restrict__ C, int M, int N, int K) {
    extern __shared__ float smem[];
    float* AsH = smem + OFF_AH;
    float* AsL = smem + OFF_AL;
    float* BsH = smem + OFF_BH;
    float* BsL = smem + OFF_BL;

    const int tid  = threadIdx.x;
    const int lane = tid & 31;
    const int warp = tid >> 5;
    const int warp_m = warp & 1;
    const int warp_n = warp >> 1;
    const int t4  = lane >> 2;
    const int tm4 = lane & 3;
    const int bm = blockIdx.y * BM;
    const int bn = blockIdx.x * BN;

    float acc[4][4][4];
#pragma unroll
    for (int mt = 0; mt < 4; mt++)
#pragma unroll
        for (int nt = 0; nt < 4; nt++)
#pragma unroll
            for (int r = 0; r < 4; r++) acc[mt][nt][r] = 0.f;

    const int nk = K / BK;

    auto prefetch = [&](int buf, int kt) {
        const int k0 = kt * BK;
#pragma unroll
        for (int l = 0; l < 4; l++) {
            int c = tid + l * 256;
            int m = c >> 3, kc = c & 7;
            size_t goff = (size_t)(bm + m) * K + k0 + kc * 2;
            int soff = buf * (BM * AS_STRIDE) + m * AS_STRIDE + kc * 2;
            asm volatile("cp.async.ca.shared.global [%0], [%1], 8;\n"
                         :: "r"(smem_u32(&AsH[soff])), "l"(Ahi + goff));
            asm volatile("cp.async.ca.shared.global [%0], [%1], 8;\n"
                         :: "r"(smem_u32(&AsL[soff])), "l"(Alo + goff));
        }
#pragma unroll
        for (int l = 0; l < 2; l++) {
            int c = tid + l * 256;
            int kk = c >> 5, n4 = c & 31;
            size_t goff = (size_t)(k0 + kk) * N + bn + n4 * 4;
            int soff = buf * (BK * BS_STRIDE) + kk * BS_STRIDE + n4 * 4;
            asm volatile("cp.async.cg.shared.global [%0], [%1], 16;\n"
                         :: "r"(smem_u32(&BsH[soff])), "l"(Bhi + goff));
            asm volatile("cp.async.cg.shared.global [%0], [%1], 16;\n"
                         :: "r"(smem_u32(&BsL[soff])), "l"(Blo + goff));
        }
        asm volatile("cp.async.commit_group;\n");
    };

    prefetch(0, 0);

    for (int kt = 0; kt < nk; kt++) {
        const int buf = kt & 1;
        if (kt + 1 < nk) {
            prefetch(buf ^ 1, kt + 1);
            asm volatile("cp.async.wait_group 1;\n");
        } else {
            asm volatile("cp.async.wait_group 0;\n");
        }
        __syncthreads();

        const float* ahB = AsH + buf * (BM * AS_STRIDE);
        const float* alB = AsL + buf * (BM * AS_STRIDE);
        const float* bhB = BsH + buf * (BK * BS_STRIDE);
        const float* blB = BsL + buf * (BK * BS_STRIDE);
#pragma unroll
        for (int ks = 0; ks < 2; ks++) {
            const int k0 = ks * 8;
            uint32_t ah[4][4], al[4][4];
#pragma unroll
            for (int mt = 0; mt < 4; mt++) {
                const int rb = warp_m * 64 + mt * 16;
                const int i0 = (rb + t4)     * AS_STRIDE + k0 + tm4;
                const int i1 = (rb + 8 + t4) * AS_STRIDE + k0 + tm4;
                ah[mt][0] = __float_as_uint(ahB[i0]);
                ah[mt][1] = __float_as_uint(ahB[i1]);
                ah[mt][2] = __float_as_uint(ahB[i0 + 4]);
                ah[mt][3] = __float_as_uint(ahB[i1 + 4]);
                al[mt][0] = __float_as_uint(alB[i0]);
                al[mt][1] = __float_as_uint(alB[i1]);
                al[mt][2] = __float_as_uint(alB[i0 + 4]);
                al[mt][3] = __float_as_uint(alB[i1 + 4]);
            }
            uint32_t bh[4][2], bl[4][2];
#pragma unroll
            for (int nt = 0; nt < 4; nt++) {
                const int nb = warp_n * 32 + nt * 8;
                const int i0 = (k0 + tm4)     * BS_STRIDE + nb + t4;
                const int i1 = (k0 + tm4 + 4) * BS_STRIDE + nb + t4;
                bh[nt][0] = __float_as_uint(bhB[i0]);
                bh[nt][1] = __float_as_uint(bhB[i1]);
                bl[nt][0] = __float_as_uint(blB[i0]);
                bl[nt][1] = __float_as_uint(blB[i1]);
            }
#pragma unroll
            for (int mt = 0; mt < 4; mt++)
#pragma unroll
                for (int nt = 0; nt < 4; nt++) {
                    mma_tf32(acc[mt][nt], al[mt], bh[nt]);
                    mma_tf32(acc[mt][nt], ah[mt], bl[nt]);
                    mma_tf32(acc[mt][nt], ah[mt], bh[nt]);
                }
        }
        __syncthreads();
    }

#pragma unroll
    for (int mt = 0; mt < 4; mt++) {
#pragma unroll
        for (int nt = 0; nt < 4; nt++) {
            const int row = bm + warp_m * 64 + mt * 16 + t4;
            const int col = bn + warp_n * 32 + nt * 8 + tm4 * 2;
            float2 v0 = make_float2(acc[mt][nt][0], acc[mt][nt][1]);
            float2 v1 = make_float2(acc[mt][nt][2], acc[mt][nt][3]);
            *(float2*)&C[(size_t)row * N + col]       = v0;
            *(float2*)&C[(size_t)(row + 8) * N + col] = v1;
        }
    }
}

// ---------------------------------------------------------------------------
// LayerNorm over last dim (1024), scale-only, in-place on q/k slices of qkv.
// ---------------------------------------------------------------------------
__global__ __launch_bounds__(256)
void ln_kernel(float* __restrict__ qkv, const float* __restrict__ q_scale,
               const float* __restrict__ k_scale) {
    const int row = blockIdx.x;
    const int which = blockIdx.y;
    const float* scale = which ? k_scale : q_scale;
    float* ptr = qkv + (size_t)row * QKV_N + which * D_MODEL;

    const int tid = threadIdx.x;
    float v[4];
    float sum = 0.f, sq = 0.f;
#pragma unroll
    for (int i = 0; i < 4; i++) {
        v[i] = ptr[tid + i * 256];
        sum += v[i];
        sq += v[i] * v[i];
    }
#pragma unroll
    for (int o = 16; o > 0; o >>= 1) {
        sum += __shfl_xor_sync(0xffffffffu, sum, o);
        sq  += __shfl_xor_sync(0xffffffffu, sq,  o);
    }
    __shared__ float ssum[8], ssq[8];
    const int warp = tid >> 5, lane = tid & 31;
    if (lane == 0) { ssum[warp] = sum; ssq[warp] = sq; }
    __syncthreads();
    if (tid == 0) {
        float a = 0.f, b = 0.f;
#pragma unroll
        for (int w = 0; w < 8; w++) { a += ssum[w]; b += ssq[w]; }
        ssum[0] = a; ssq[0] = b;
    }
    __syncthreads();
    const float mean = ssum[0] * (1.f / D_MODEL);
    const float var  = ssq[0] * (1.f / D_MODEL) - mean * mean;
    const float inv  = rsqrtf(var + LN_EPS);
#pragma unroll
    for (int i = 0; i < 4; i++) {
        int c = tid + i * 256;
        ptr[c] = (v[i] - mean) * inv * scale[c];
    }
}

// ===========================================================================
// Flash attention with 3xTF32 tensor cores. Causal. (As R6, but epilogue
// writes pre-split ctx_hi/ctx_lo for the out-proj GEMM.)
// ===========================================================================
#define QP_STR 68
#define K_STR  68
#define V_STR  72
#define ATTN_SMEM_FLOATS 22272   // 89088 B

__global__ __launch_bounds__(128)
void attn_mma_kernel(const float* __restrict__ qkv,
                     float* __restrict__ ctx_hi, float* __restrict__ ctx_lo) {
    extern __shared__ float sm[];
    float* QPs = sm;                 // Q tile, later P tile
    float* Ksm = sm + 4352;          // 2 buffers of 64*68
    float* Vsm = sm + 13056;         // 2 buffers of 64*72

    const int qt = blockIdx.x;
    const int h  = blockIdx.y;
    const int b  = blockIdx.z;
    const int tid  = threadIdx.x;
    const int lane = tid & 31;
    const int w    = tid >> 5;
    const int t4   = lane >> 2;
    const int tm4  = lane & 3;
    const int w16  = w * 16;

    const float* qbase = qkv + ((size_t)(b * SEQ + qt * 64)) * QKV_N + (size_t)h * HD;

    auto prefetch_kv = [&](int buf, int kt) {
        const float* kb = qkv + ((size_t)(b * SEQ + kt * 64)) * QKV_N + D_MODEL + (size_t)h * HD;
        const float* vb = kb + D_MODEL;
        float* Kd = Ksm + buf * (64 * K_STR);
        float* Vd = Vsm + buf * (64 * V_STR);
#pragma unroll
        for (int l = 0; l < 8; l++) {
            int c = tid + l * 128;
            int row = c >> 4, c4 = c & 15;
            const float* srcK = kb + (size_t)row * QKV_N + c4 * 4;
            uint32_t dstK = smem_u32(&Kd[row * K_STR + c4 * 4]);
            asm volatile("cp.async.cg.shared.global [%0], [%1], 16;\n"
                         :: "r"(dstK), "l"(srcK));
            const float* srcV = vb + (size_t)row * QKV_N + c4 * 4;
            uint32_t dstV = smem_u32(&Vd[row * V_STR + c4 * 4]);
            asm volatile("cp.async.cg.shared.global [%0], [%1], 16;\n"
                         :: "r"(dstV), "l"(srcV));
        }
        asm volatile("cp.async.commit_group;\n");
    };

    prefetch_kv(0, 0);
#pragma unroll
    for (int l = 0; l < 8; l++) {
        int c = tid + l * 128;
        int row = c >> 4, c4 = c & 15;
        float4 v = *(const float4*)(qbase + (size_t)row * QKV_N + c4 * 4);
        *(float4*)&QPs[row * QP_STR + c4 * 4] = v;
    }
    __syncthreads();

    uint32_t qah[8][4], qal[8][4];
#pragma unroll
    for (int ks = 0; ks < 8; ks++) {
        const int k0 = ks * 8;
        float v0 = 0.125f * QPs[(w16 + t4)     * QP_STR + k0 + tm4];
        float v1 = 0.125f * QPs[(w16 + t4 + 8) * QP_STR + k0 + tm4];
        float v2 = 0.125f * QPs[(w16 + t4)     * QP_STR + k0 + tm4 + 4];
        float v3 = 0.125f * QPs[(w16 + t4 + 8) * QP_STR + k0 + tm4 + 4];
        split_tf32(v0, qah[ks][0], qal[ks][0]);
        split_tf32(v1, qah[ks][1], qal[ks][1]);
        split_tf32(v2, qah[ks][2], qal[ks][2]);
        split_tf32(v3, qah[ks][3], qal[ks][3]);
    }
    __syncthreads();

    float m0 = -1e30f, m1 = -1e30f, l0 = 0.f, l1 = 0.f;
    float oacc[8][4];
#pragma unroll
    for (int nt = 0; nt < 8; nt++)
#pragma unroll
        for (int r = 0; r < 4; r++) oacc[nt][r] = 0.f;

    for (int kt = 0; kt <= qt; kt++) {
        const int buf = kt & 1;
        asm volatile("cp.async.wait_group 0;\n");
        __syncthreads();
        if (kt < qt) prefetch_kv(buf ^ 1, kt + 1);

        const float* Kb = Ksm + buf * (64 * K_STR);
        const float* Vb = Vsm + buf * (64 * V_STR);

        float s[8][4];
#pragma unroll
        for (int nt = 0; nt < 8; nt++)
#pragma unroll
            for (int r = 0; r < 4; r++) s[nt][r] = 0.f;

#pragma unroll
        for (int ks = 0; ks < 8; ks++) {
            const int k0 = ks * 8;
            uint32_t kh[8][2], kl[8][2];
#pragma unroll
            for (int nt = 0; nt < 8; nt++) {
                float v0 = Kb[(nt * 8 + t4) * K_STR + k0 + tm4];
                float v1 = Kb[(nt * 8 + t4) * K_STR + k0 + tm4 + 4];
                split_tf32(v0, kh[nt][0], kl[nt][0]);
                split_tf32(v1, kh[nt][1], kl[nt][1]);
            }
#pragma unroll
            for (int nt = 0; nt < 8; nt++) {
                mma_tf32(s[nt], qal[ks], kh[nt]);
                mma_tf32(s[nt], qah[ks], kl[nt]);
                mma_tf32(s[nt], qah[ks], kh[nt]);
            }
        }

        if (kt == qt) {
#pragma unroll
            for (int nt = 0; nt < 8; nt++) {
                const int c0 = nt * 8 + tm4 * 2;
                const int r0 = w16 + t4;
                if (c0     > r0)     s[nt][0] = -1e30f;
                if (c0 + 1 > r0)     s[nt][1] = -1e30f;
                if (c0     > r0 + 8) s[nt][2] = -1e30f;
                if (c0 + 1 > r0 + 8) s[nt][3] = -1e30f;
            }
        }

        float rm0 = -1e30f, rm1 = -1e30f;
#pragma unroll
        for (int nt = 0; nt < 8; nt++) {
            rm0 = fmaxf(rm0, fmaxf(s[nt][0], s[nt][1]));
            rm1 = fmaxf(rm1, fmaxf(s[nt][2], s[nt][3]));
        }
#pragma unroll
        for (int o = 1; o <= 2; o <<= 1) {
            rm0 = fmaxf(rm0, __shfl_xor_sync(0xffffffffu, rm0, o));
            rm1 = fmaxf(rm1, __shfl_xor_sync(0xffffffffu, rm1, o));
        }
        const float nm0 = fmaxf(m0, rm0);
        const float nm1 = fmaxf(m1, rm1);
        const float c0 = expf(m0 - nm0);
        const float c1 = expf(m1 - nm1);
        float rs0 = 0.f, rs1 = 0.f;
#pragma unroll
        for (int nt = 0; nt < 8; nt++) {
            s[nt][0] = expf(s[nt][0] - nm0);
            s[nt][1] = expf(s[nt][1] - nm0);
            s[nt][2] = expf(s[nt][2] - nm1);
            s[nt][3] = expf(s[nt][3] - nm1);
            rs0 += s[nt][0] + s[nt][1];
            rs1 += s[nt][2] + s[nt][3];
        }
#pragma unroll
        for (int o = 1; o <= 2; o <<= 1) {
            rs0 += __shfl_xor_sync(0xffffffffu, rs0, o);
            rs1 += __shfl_xor_sync(0xffffffffu, rs1, o);
        }
        l0 = l0 * c0 + rs0;  m0 = nm0;
        l1 = l1 * c1 + rs1;  m1 = nm1;
#pragma unroll
        for (int nt = 0; nt < 8; nt++) {
            oacc[nt][0] *= c0; oacc[nt][1] *= c0;
            oacc[nt][2] *= c1; oacc[nt][3] *= c1;
        }

#pragma unroll
        for (int nt = 0; nt < 8; nt++) {
            *(float2*)&QPs[(w16 + t4)     * QP_STR + nt * 8 + tm4 * 2] =
                make_float2(s[nt][0], s[nt][1]);
            *(float2*)&QPs[(w16 + t4 + 8) * QP_STR + nt * 8 + tm4 * 2] =
                make_float2(s[nt][2], s[nt][3]);
        }
        __syncwarp();

#pragma unroll
        for (int ks = 0; ks < 8; ks++) {
            const int k0 = ks * 8;
            uint32_t pah[4], pal[4];
            {
                float v0 = QPs[(w16 + t4)     * QP_STR + k0 + tm4];
                float v1 = QPs[(w16 + t4 + 8) * QP_STR + k0 + tm4];
                float v2 = QPs[(w16 + t4)     * QP_STR + k0 + tm4 + 4];
                float v3 = QPs[(w16 + t4 + 8) * QP_STR + k0 + tm4 + 4];
                split_tf32(v0, pah[0], pal[0]);
                split_tf32(v1, pah[1], pal[1]);
                split_tf32(v2, pah[2], pal[2]);
                split_tf32(v3, pah[3], pal[3]);
            }
#pragma unroll
            for (int nt = 0; nt < 8; nt++) {
                uint32_t vh[2], vl[2];
                float v0 = Vb[(k0 + tm4)     * V_STR + nt * 8 + t4];
                float v1 = Vb[(k0 + tm4 + 4) * V_STR + nt * 8 + t4];
                split_tf32(v0, vh[0], vl[0]);
                split_tf32(v1, vh[1], vl[1]);
                mma_tf32(oacc[nt], pal, vh);
                mma_tf32(oacc[nt], pah, vl);
                mma_tf32(oacc[nt], pah, vh);
            }
        }
        __syncwarp();
    }

    // epilogue: normalize and write PRE-SPLIT ctx (hi/lo) for the out-proj
    const float i0 = 1.f / l0, i1 = 1.f / l1;
    const size_t r0 = (size_t)(b * SEQ + qt * 64 + w16 + t4) * D_MODEL;
    const size_t r1 = (size_t)(b * SEQ + qt * 64 + w16 + t4 + 8) * D_MODEL;
#pragma unroll
    for (int nt = 0; nt < 8; nt++) {
        const int col = h * HD + nt * 8 + tm4 * 2;
        float o00 = oacc[nt][0] * i0, o01 = oacc[nt][1] * i0;
        float o10 = oacc[nt][2] * i1, o11 = oacc[nt][3] * i1;
        uint32_t h00, l00, h01, l01, h10, l10, h11, l11;
        split_tf32(o00, h00, l00);
        split_tf32(o01, h01, l01);
        split_tf32(o10, h10, l10);
        split_tf32(o11, h11, l11);
        *(float2*)&ctx_hi[r0 + col] = make_float2(__uint_as_float(h00), __uint_as_float(h01));
        *(float2*)&ctx_lo[r0 + col] = make_float2(__uint_as_float(l00), __uint_as_float(l01));
        *(float2*)&ctx_hi[r1 + col] = make_float2(__uint_as_float(h10), __uint_as_float(h11));
        *(float2*)&ctx_lo[r1 + col] = make_float2(__uint_as_float(l10), __uint_as_float(l11));
    }
}

// ---------------------------------------------------------------------------
extern "C" void kernel_launch(void* const* d_in, const int* in_sizes, int n_in,
                              void* d_out, int out_size) {
    const float* x     = (const float*)d_in[0];
    const float* Wqkv  = (const float*)d_in[1];
    const float* qscl  = (const float*)d_in[2];
    const float* kscl  = (const float*)d_in[3];
    const float* Wout  = (const float*)d_in[4];
    float* out = (float*)d_out;

    float *qkv, *xhi, *xlo, *wqh, *wql, *woh, *wol, *chi, *clo;
    cudaGetSymbolAddress((void**)&qkv, g_qkv);
    cudaGetSymbolAddress((void**)&xhi, g_xhi);
    cudaGetSymbolAddress((void**)&xlo, g_xlo);
    cudaGetSymbolAddress((void**)&wqh, g_wqkv_hi);
    cudaGetSymbolAddress((void**)&wql, g_wqkv_lo);
    cudaGetSymbolAddress((void**)&woh, g_wout_hi);
    cudaGetSymbolAddress((void**)&wol, g_wout_lo);
    cudaGetSymbolAddress((void**)&chi, g_ctx_hi);
    cudaGetSymbolAddress((void**)&clo, g_ctx_lo);

    const int gemm_smem = GEMM_SMEM_FLOATS * (int)sizeof(float);   // 75776
    cudaFuncSetAttribute(gemm_tf32x3_pre_kernel,
                         cudaFuncAttributeMaxDynamicSharedMemorySize, gemm_smem);

    // 0) split inputs into tf32 hi/lo (one pass each)
    {
        int n4x = ROWS * D_MODEL / 4;
        split_kernel<<<(n4x + 255) / 256, 256>>>(x, xhi, xlo, n4x);
        int n4w = D_MODEL * QKV_N / 4;
        split_kernel<<<(n4w + 255) / 256, 256>>>(Wqkv, wqh, wql, n4w);
        int n4o = D_MODEL * D_MODEL / 4;
        split_kernel<<<(n4o + 255) / 256, 256>>>(Wout, woh, wol, n4o);
    }
    // 1) qkv = x @ W_qkv   (3xTF32, pre-split)
    {
        dim3 grid(QKV_N / BN, ROWS / BM);
        gemm_tf32x3_pre_kernel<<<grid, 256, gemm_smem>>>(
            xhi, xlo, wqh, wql, qkv, ROWS, QKV_N, D_MODEL);
    }
    // 2) QK-LayerNorm in place
    {
        dim3 grid(ROWS, 2);
        ln_kernel<<<grid, 256>>>(qkv, qscl, kscl);
    }
    // 3) causal flash attention (3xTF32) -> ctx_hi/ctx_lo
    {
        const int smem = ATTN_SMEM_FLOATS * (int)sizeof(float);  // 89088 B
        cudaFuncSetAttribute(attn_mma_kernel,
                             cudaFuncAttributeMaxDynamicSharedMemorySize, smem);
        dim3 grid(SEQ / 64, N_HEADS, BATCH);
        attn_mma_kernel<<<grid, 128, smem>>>(qkv, chi, clo);
    }
    // 4) out = ctx @ W_out  (3xTF32, pre-split)
    {
        dim3 grid(D_MODEL / BN, ROWS / BM);
        gemm_tf32x3_pre_kernel<<<grid, 256, gemm_smem>>>(
            chi, clo, woh, wol, out, ROWS, D_MODEL, D_MODEL);
    }
}

// round 10
// speedup vs baseline: 1.0099x; 1.0099x over previous
#include <cuda_runtime.h>
#include <math.h>
#include <cstdint>

#define D_MODEL 1024
#define N_HEADS 16
#define HD      64
#define BATCH   2
#define SEQ     2048
#define ROWS    (BATCH*SEQ)      // 4096
#define QKV_N   (3*D_MODEL)      // 3072
#define LN_EPS  1e-6f

// Scratch (device-global: no runtime allocation allowed).
// *_2 arrays are interleaved {hi, lo} tf32-valued pairs.
__device__ float  g_qkv[(size_t)ROWS * QKV_N];          // 48 MB fp32 qkv
__device__ float2 g_x2[(size_t)ROWS * D_MODEL];         // x split (32 MB)
__device__ float2 g_wqkv2[(size_t)D_MODEL * QKV_N];     // W_qkv split (24 MB)
__device__ float2 g_wout2[(size_t)D_MODEL * D_MODEL];   // W_out split (8 MB)
__device__ float2 g_ctx2[(size_t)ROWS * D_MODEL];       // attention out split (32 MB)

__device__ __forceinline__ uint32_t smem_u32(const void* p) {
    return (uint32_t)__cvta_generic_to_shared(p);
}

__device__ __forceinline__ void mma_tf32(float* d, const uint32_t* a, const uint32_t* b) {
    asm volatile(
        "mma.sync.aligned.m16n8k8.row.col.f32.tf32.tf32.f32 "
        "{%0,%1,%2,%3}, {%4,%5,%6,%7}, {%8,%9}, {%0,%1,%2,%3};\n"
        : "+f"(d[0]), "+f"(d[1]), "+f"(d[2]), "+f"(d[3])
        : "r"(a[0]), "r"(a[1]), "r"(a[2]), "r"(a[3]), "r"(b[0]), "r"(b[1]));
}

__device__ __forceinline__ uint32_t cvt_tf32(float x) {
    uint32_t h;
    asm("cvt.rna.tf32.f32 %0, %1;\n" : "=r"(h) : "f"(x));
    return h;
}

// fp32 -> (tf32 hi, tf32 lo) with lo = rna_tf32(x - hi)
__device__ __forceinline__ void split_tf32(float x, uint32_t& hi, uint32_t& lo) {
    uint32_t h = cvt_tf32(x);
    float resid = x - __uint_as_float(h);
    hi = h; lo = cvt_tf32(resid);
}

// ---------------------------------------------------------------------------
// Elementwise split: src fp32 -> interleaved float2{hi,lo}. 4 elems/thread.
// ---------------------------------------------------------------------------
__global__ __launch_bounds__(256)
void split2_kernel(const float* __restrict__ src, float2* __restrict__ dst, int n4) {
    int i = blockIdx.x * blockDim.x + threadIdx.x;
    if (i >= n4) return;
    float4 v = ((const float4*)src)[i];
    uint32_t h0, l0, h1, l1, h2, l2, h3, l3;
    split_tf32(v.x, h0, l0);
    split_tf32(v.y, h1, l1);
    split_tf32(v.z, h2, l2);
    split_tf32(v.w, h3, l3);
    float4* d4 = (float4*)dst;
    d4[2 * i]     = make_float4(__uint_as_float(h0), __uint_as_float(l0),
                                __uint_as_float(h1), __uint_as_float(l1));
    d4[2 * i + 1] = make_float4(__uint_as_float(h2), __uint_as_float(l2),
                                __uint_as_float(h3), __uint_as_float(l3));
}

// ===========================================================================
// 3xTF32 GEMM on interleaved pre-split operands: C = A @ B.
// A2[M][K], B2[K][N] as float2{hi,lo}. 128x128 CTA tile, BK=16, 256 thr,
// 8 warps (2m x 4n), warp tile 64x32. Fragments via LDS.64 (one load = hi+lo).
// 3-stage cp.async pipeline. Strides (float2 units) ≡ 4 mod 16 for clean
// 64-bit bank phases: A rows 20, B rows 132. Smem 112128 B, 2 CTAs/SM.
// ===========================================================================
#define BM 128
#define BN 128
#define BK 16
#define A2_STR 20
#define B2_STR 132
#define STAGE_A (BM * A2_STR)            // 2560 float2
#define STAGE_B (BK * B2_STR)            // 2112 float2
#define STAGE_FLOAT2 (STAGE_A + STAGE_B) // 4672 float2 = 37376 B
#define GEMM_SMEM_BYTES (3 * STAGE_FLOAT2 * 8)  // 112128

__global__ __launch_bounds__(256, 2)
void gemm_tf32x3_i_kernel(const float2* __restrict__ A2, const float2* __restrict__ B2,
                          float* __restrict__ C, int M, int N, int K) {
    extern __shared__ float2 sm2[];

    const int tid  = threadIdx.x;
    const int lane = tid & 31;
    const int warp = tid >> 5;
    const int warp_m = warp & 1;
    const int warp_n = warp >> 1;
    const int t4  = lane >> 2;
    const int tm4 = lane & 3;
    const int bm = blockIdx.y * BM;
    const int bn = blockIdx.x * BN;

    float acc[4][4][4];
#pragma unroll
    for (int mt = 0; mt < 4; mt++)
#pragma unroll
        for (int nt = 0; nt < 4; nt++)
#pragma unroll
            for (int r = 0; r < 4; r++) acc[mt][nt][r] = 0.f;

    const int nk = K / BK;

    auto prefetch = [&](int stage, int kt) {
        const int k0 = kt * BK;
        float2* As = sm2 + stage * STAGE_FLOAT2;
        float2* Bs = As + STAGE_A;
        // A tile: 128 rows x 16 float2 = 1024 x 16B chunks, 4/thread
#pragma unroll
        for (int l = 0; l < 4; l++) {
            int c = tid + l * 256;
            int m = c >> 3, ch = c & 7;
            const float2* src = A2 + (size_t)(bm + m) * K + k0 + ch * 2;
            uint32_t dst = smem_u32(&As[m * A2_STR + ch * 2]);
            asm volatile("cp.async.cg.shared.global [%0], [%1], 16;\n"
                         :: "r"(dst), "l"(src));
        }
        // B tile: 16 rows x 128 float2 = 1024 x 16B chunks, 4/thread
#pragma unroll
        for (int l = 0; l < 4; l++) {
            int c = tid + l * 256;
            int kk = c >> 6, ch = c & 63;
            const float2* src = B2 + (size_t)(k0 + kk) * N + bn + ch * 2;
            uint32_t dst = smem_u32(&Bs[kk * B2_STR + ch * 2]);
            asm volatile("cp.async.cg.shared.global [%0], [%1], 16;\n"
                         :: "r"(dst), "l"(src));
        }
        asm volatile("cp.async.commit_group;\n");
    };

    prefetch(0, 0);
    if (nk > 1) prefetch(1, 1);

    int stage = 0;
    for (int kt = 0; kt < nk; kt++) {
        if (kt + 1 < nk) {
            asm volatile("cp.async.wait_group 1;\n");
        } else {
            asm volatile("cp.async.wait_group 0;\n");
        }
        __syncthreads();
        if (kt + 2 < nk) {
            int ns = stage + 2; if (ns >= 3) ns -= 3;
            prefetch(ns, kt + 2);
        }

        const float2* As = sm2 + stage * STAGE_FLOAT2;
        const float2* Bs = As + STAGE_A;
#pragma unroll
        for (int ks = 0; ks < 2; ks++) {
            const int k0 = ks * 8;
            uint32_t ah[4][4], al[4][4];
#pragma unroll
            for (int mt = 0; mt < 4; mt++) {
                const int rb = warp_m * 64 + mt * 16;
                float2 p0 = As[(rb + t4)     * A2_STR + k0 + tm4];
                float2 p1 = As[(rb + 8 + t4) * A2_STR + k0 + tm4];
                float2 p2 = As[(rb + t4)     * A2_STR + k0 + tm4 + 4];
                float2 p3 = As[(rb + 8 + t4) * A2_STR + k0 + tm4 + 4];
                ah[mt][0] = __float_as_uint(p0.x); al[mt][0] = __float_as_uint(p0.y);
                ah[mt][1] = __float_as_uint(p1.x); al[mt][1] = __float_as_uint(p1.y);
                ah[mt][2] = __float_as_uint(p2.x); al[mt][2] = __float_as_uint(p2.y);
                ah[mt][3] = __float_as_uint(p3.x); al[mt][3] = __float_as_uint(p3.y);
            }
            uint32_t bh[4][2], bl[4][2];
#pragma unroll
            for (int nt = 0; nt < 4; nt++) {
                const int nb = warp_n * 32 + nt * 8;
                float2 q0 = Bs[(k0 + tm4)     * B2_STR + nb + t4];
                float2 q1 = Bs[(k0 + tm4 + 4) * B2_STR + nb + t4];
                bh[nt][0] = __float_as_uint(q0.x); bl[nt][0] = __float_as_uint(q0.y);
                bh[nt][1] = __float_as_uint(q1.x); bl[nt][1] = __float_as_uint(q1.y);
            }
#pragma unroll
            for (int mt = 0; mt < 4; mt++)
#pragma unroll
                for (int nt = 0; nt < 4; nt++) {
                    mma_tf32(acc[mt][nt], al[mt], bh[nt]);
                    mma_tf32(acc[mt][nt], ah[mt], bl[nt]);
                    mma_tf32(acc[mt][nt], ah[mt], bh[nt]);
                }
        }
        __syncthreads();
        if (++stage == 3) stage = 0;
    }

#pragma unroll
    for (int mt = 0; mt < 4; mt++) {
#pragma unroll
        for (int nt = 0; nt < 4; nt++) {
            const int row = bm + warp_m * 64 + mt * 16 + t4;
            const int col = bn + warp_n * 32 + nt * 8 + tm4 * 2;
            float2 v0 = make_float2(acc[mt][nt][0], acc[mt][nt][1]);
            float2 v1 = make_float2(acc[mt][nt][2], acc[mt][nt][3]);
            *(float2*)&C[(size_t)row * N + col]       = v0;
            *(float2*)&C[(size_t)(row + 8) * N + col] = v1;
        }
    }
}

// ---------------------------------------------------------------------------
// LayerNorm over last dim (1024), scale-only, in-place on q/k slices of qkv.
// ---------------------------------------------------------------------------
__global__ __launch_bounds__(256)
void ln_kernel(float* __restrict__ qkv, const float* __restrict__ q_scale,
               const float* __restrict__ k_scale) {
    const int row = blockIdx.x;
    const int which = blockIdx.y;
    const float* scale = which ? k_scale : q_scale;
    float* ptr = qkv + (size_t)row * QKV_N + which * D_MODEL;

    const int tid = threadIdx.x;
    float v[4];
    float sum = 0.f, sq = 0.f;
#pragma unroll
    for (int i = 0; i < 4; i++) {
        v[i] = ptr[tid + i * 256];
        sum += v[i];
        sq += v[i] * v[i];
    }
#pragma unroll
    for (int o = 16; o > 0; o >>= 1) {
        sum += __shfl_xor_sync(0xffffffffu, sum, o);
        sq  += __shfl_xor_sync(0xffffffffu, sq,  o);
    }
    __shared__ float ssum[8], ssq[8];
    const int warp = tid >> 5, lane = tid & 31;
    if (lane == 0) { ssum[warp] = sum; ssq[warp] = sq; }
    __syncthreads();
    if (tid == 0) {
        float a = 0.f, b = 0.f;
#pragma unroll
        for (int w = 0; w < 8; w++) { a += ssum[w]; b += ssq[w]; }
        ssum[0] = a; ssq[0] = b;
    }
    __syncthreads();
    const float mean = ssum[0] * (1.f / D_MODEL);
    const float var  = ssq[0] * (1.f / D_MODEL) - mean * mean;
    const float inv  = rsqrtf(var + LN_EPS);
#pragma unroll
    for (int i = 0; i < 4; i++) {
        int c = tid + i * 256;
        ptr[c] = (v[i] - mean) * inv * scale[c];
    }
}

// ===========================================================================
// Flash attention with 3xTF32 QK^T and 2-term PV (P = tf32-hi only). Causal.
// CTA: 64-q-row tile x (head, batch). 128 threads = 4 warps. Epilogue writes
// interleaved {hi,lo} ctx for the out-proj GEMM.
// ===========================================================================
#define QP_STR 68
#define K_STR  68
#define V_STR  72
#define ATTN_SMEM_FLOATS 22272   // 89088 B

__global__ __launch_bounds__(128)
void attn_mma_kernel(const float* __restrict__ qkv, float2* __restrict__ ctx2) {
    extern __shared__ float sm[];
    float* QPs = sm;                 // Q tile, later P tile
    float* Ksm = sm + 4352;          // 2 buffers of 64*68
    float* Vsm = sm + 13056;         // 2 buffers of 64*72

    const int qt = blockIdx.x;
    const int h  = blockIdx.y;
    const int b  = blockIdx.z;
    const int tid  = threadIdx.x;
    const int lane = tid & 31;
    const int w    = tid >> 5;
    const int t4   = lane >> 2;
    const int tm4  = lane & 3;
    const int w16  = w * 16;

    const float* qbase = qkv + ((size_t)(b * SEQ + qt * 64)) * QKV_N + (size_t)h * HD;

    auto prefetch_kv = [&](int buf, int kt) {
        const float* kb = qkv + ((size_t)(b * SEQ + kt * 64)) * QKV_N + D_MODEL + (size_t)h * HD;
        const float* vb = kb + D_MODEL;
        float* Kd = Ksm + buf * (64 * K_STR);
        float* Vd = Vsm + buf * (64 * V_STR);
#pragma unroll
        for (int l = 0; l < 8; l++) {
            int c = tid + l * 128;
            int row = c >> 4, c4 = c & 15;
            const float* srcK = kb + (size_t)row * QKV_N + c4 * 4;
            uint32_t dstK = smem_u32(&Kd[row * K_STR + c4 * 4]);
            asm volatile("cp.async.cg.shared.global [%0], [%1], 16;\n"
                         :: "r"(dstK), "l"(srcK));
            const float* srcV = vb + (size_t)row * QKV_N + c4 * 4;
            uint32_t dstV = smem_u32(&Vd[row * V_STR + c4 * 4]);
            asm volatile("cp.async.cg.shared.global [%0], [%1], 16;\n"
                         :: "r"(dstV), "l"(srcV));
        }
        asm volatile("cp.async.commit_group;\n");
    };

    prefetch_kv(0, 0);
#pragma unroll
    for (int l = 0; l < 8; l++) {
        int c = tid + l * 128;
        int row = c >> 4, c4 = c & 15;
        float4 v = *(const float4*)(qbase + (size_t)row * QKV_N + c4 * 4);
        *(float4*)&QPs[row * QP_STR + c4 * 4] = v;
    }
    __syncthreads();

    uint32_t qah[8][4], qal[8][4];
#pragma unroll
    for (int ks = 0; ks < 8; ks++) {
        const int k0 = ks * 8;
        float v0 = 0.125f * QPs[(w16 + t4)     * QP_STR + k0 + tm4];
        float v1 = 0.125f * QPs[(w16 + t4 + 8) * QP_STR + k0 + tm4];
        float v2 = 0.125f * QPs[(w16 + t4)     * QP_STR + k0 + tm4 + 4];
        float v3 = 0.125f * QPs[(w16 + t4 + 8) * QP_STR + k0 + tm4 + 4];
        split_tf32(v0, qah[ks][0], qal[ks][0]);
        split_tf32(v1, qah[ks][1], qal[ks][1]);
        split_tf32(v2, qah[ks][2], qal[ks][2]);
        split_tf32(v3, qah[ks][3], qal[ks][3]);
    }
    __syncthreads();

    float m0 = -1e30f, m1 = -1e30f, l0 = 0.f, l1 = 0.f;
    float oacc[8][4];
#pragma unroll
    for (int nt = 0; nt < 8; nt++)
#pragma unroll
        for (int r = 0; r < 4; r++) oacc[nt][r] = 0.f;

    for (int kt = 0; kt <= qt; kt++) {
        const int buf = kt & 1;
        asm volatile("cp.async.wait_group 0;\n");
        __syncthreads();
        if (kt < qt) prefetch_kv(buf ^ 1, kt + 1);

        const float* Kb = Ksm + buf * (64 * K_STR);
        const float* Vb = Vsm + buf * (64 * V_STR);

        // ---- S = (Q*0.125) @ K^T  (3xTF32) ----
        float s[8][4];
#pragma unroll
        for (int nt = 0; nt < 8; nt++)
#pragma unroll
            for (int r = 0; r < 4; r++) s[nt][r] = 0.f;

#pragma unroll
        for (int ks = 0; ks < 8; ks++) {
            const int k0 = ks * 8;
            uint32_t kh[8][2], kl[8][2];
#pragma unroll
            for (int nt = 0; nt < 8; nt++) {
                float v0 = Kb[(nt * 8 + t4) * K_STR + k0 + tm4];
                float v1 = Kb[(nt * 8 + t4) * K_STR + k0 + tm4 + 4];
                split_tf32(v0, kh[nt][0], kl[nt][0]);
                split_tf32(v1, kh[nt][1], kl[nt][1]);
            }
#pragma unroll
            for (int nt = 0; nt < 8; nt++) {
                mma_tf32(s[nt], qal[ks], kh[nt]);
                mma_tf32(s[nt], qah[ks], kl[nt]);
                mma_tf32(s[nt], qah[ks], kh[nt]);
            }
        }

        if (kt == qt) {
#pragma unroll
            for (int nt = 0; nt < 8; nt++) {
                const int c0 = nt * 8 + tm4 * 2;
                const int r0 = w16 + t4;
                if (c0     > r0)     s[nt][0] = -1e30f;
                if (c0 + 1 > r0)     s[nt][1] = -1e30f;
                if (c0     > r0 + 8) s[nt][2] = -1e30f;
                if (c0 + 1 > r0 + 8) s[nt][3] = -1e30f;
            }
        }

        // ---- online softmax ----
        float rm0 = -1e30f, rm1 = -1e30f;
#pragma unroll
        for (int nt = 0; nt < 8; nt++) {
            rm0 = fmaxf(rm0, fmaxf(s[nt][0], s[nt][1]));
            rm1 = fmaxf(rm1, fmaxf(s[nt][2], s[nt][3]));
        }
#pragma unroll
        for (int o = 1; o <= 2; o <<= 1) {
            rm0 = fmaxf(rm0, __shfl_xor_sync(0xffffffffu, rm0, o));
            rm1 = fmaxf(rm1, __shfl_xor_sync(0xffffffffu, rm1, o));
        }
        const float nm0 = fmaxf(m0, rm0);
        const float nm1 = fmaxf(m1, rm1);
        const float c0 = expf(m0 - nm0);
        const float c1 = expf(m1 - nm1);
        float rs0 = 0.f, rs1 = 0.f;
#pragma unroll
        for (int nt = 0; nt < 8; nt++) {
            s[nt][0] = expf(s[nt][0] - nm0);
            s[nt][1] = expf(s[nt][1] - nm0);
            s[nt][2] = expf(s[nt][2] - nm1);
            s[nt][3] = expf(s[nt][3] - nm1);
            rs0 += s[nt][0] + s[nt][1];
            rs1 += s[nt][2] + s[nt][3];
        }
#pragma unroll
        for (int o = 1; o <= 2; o <<= 1) {
            rs0 += __shfl_xor_sync(0xffffffffu, rs0, o);
            rs1 += __shfl_xor_sync(0xffffffffu, rs1, o);
        }
        l0 = l0 * c0 + rs0;  m0 = nm0;
        l1 = l1 * c1 + rs1;  m1 = nm1;
#pragma unroll
        for (int nt = 0; nt < 8; nt++) {
            oacc[nt][0] *= c0; oacc[nt][1] *= c0;
            oacc[nt][2] *= c1; oacc[nt][3] *= c1;
        }

#pragma unroll
        for (int nt = 0; nt < 8; nt++) {
            *(float2*)&QPs[(w16 + t4)     * QP_STR + nt * 8 + tm4 * 2] =
                make_float2(s[nt][0], s[nt][1]);
            *(float2*)&QPs[(w16 + t4 + 8) * QP_STR + nt * 8 + tm4 * 2] =
                make_float2(s[nt][2], s[nt][3]);
        }
        __syncwarp();

        // ---- O += P @ V : P tf32-hi only, V split -> 2 MMAs ----
#pragma unroll
        for (int ks = 0; ks < 8; ks++) {
            const int k0 = ks * 8;
            uint32_t pah[4];
            pah[0] = cvt_tf32(QPs[(w16 + t4)     * QP_STR + k0 + tm4]);
            pah[1] = cvt_tf32(QPs[(w16 + t4 + 8) * QP_STR + k0 + tm4]);
            pah[2] = cvt_tf32(QPs[(w16 + t4)     * QP_STR + k0 + tm4 + 4]);
            pah[3] = cvt_tf32(QPs[(w16 + t4 + 8) * QP_STR + k0 + tm4 + 4]);
#pragma unroll
            for (int nt = 0; nt < 8; nt++) {
                uint32_t vh[2], vl[2];
                float v0 = Vb[(k0 + tm4)     * V_STR + nt * 8 + t4];
                float v1 = Vb[(k0 + tm4 + 4) * V_STR + nt * 8 + t4];
                split_tf32(v0, vh[0], vl[0]);
                split_tf32(v1, vh[1], vl[1]);
                mma_tf32(oacc[nt], pah, vl);
                mma_tf32(oacc[nt], pah, vh);
            }
        }
        __syncwarp();
    }

    // epilogue: normalize, split, write interleaved {hi,lo} ctx
    const float i0 = 1.f / l0, i1 = 1.f / l1;
    const size_t r0 = (size_t)(b * SEQ + qt * 64 + w16 + t4) * D_MODEL;
    const size_t r1 = (size_t)(b * SEQ + qt * 64 + w16 + t4 + 8) * D_MODEL;
#pragma unroll
    for (int nt = 0; nt < 8; nt++) {
        const int col = h * HD + nt * 8 + tm4 * 2;
        float o00 = oacc[nt][0] * i0, o01 = oacc[nt][1] * i0;
        float o10 = oacc[nt][2] * i1, o11 = oacc[nt][3] * i1;
        uint32_t h00, l00, h01, l01, h10, l10, h11, l11;
        split_tf32(o00, h00, l00);
        split_tf32(o01, h01, l01);
        split_tf32(o10, h10, l10);
        split_tf32(o11, h11, l11);
        *(float4*)&ctx2[r0 + col] = make_float4(__uint_as_float(h00), __uint_as_float(l00),
                                                __uint_as_float(h01), __uint_as_float(l01));
        *(float4*)&ctx2[r1 + col] = make_float4(__uint_as_float(h10), __uint_as_float(l10),
                                                __uint_as_float(h11), __uint_as_float(l11));
    }
}

// ---------------------------------------------------------------------------
extern "C" void kernel_launch(void* const* d_in, const int* in_sizes, int n_in,
                              void* d_out, int out_size) {
    const float* x     = (const float*)d_in[0];
    const float* Wqkv  = (const float*)d_in[1];
    const float* qscl  = (const float*)d_in[2];
    const float* kscl  = (const float*)d_in[3];
    const float* Wout  = (const float*)d_in[4];
    float* out = (float*)d_out;

    float *qkv;
    float2 *x2, *wq2, *wo2, *c2;
    cudaGetSymbolAddress((void**)&qkv, g_qkv);
    cudaGetSymbolAddress((void**)&x2,  g_x2);
    cudaGetSymbolAddress((void**)&wq2, g_wqkv2);
    cudaGetSymbolAddress((void**)&wo2, g_wout2);
    cudaGetSymbolAddress((void**)&c2,  g_ctx2);

    cudaFuncSetAttribute(gemm_tf32x3_i_kernel,
                         cudaFuncAttributeMaxDynamicSharedMemorySize, GEMM_SMEM_BYTES);

    // 0) split inputs into interleaved tf32 {hi,lo}
    {
        int n4x = ROWS * D_MODEL / 4;
        split2_kernel<<<(n4x + 255) / 256, 256>>>(x, x2, n4x);
        int n4w = D_MODEL * QKV_N / 4;
        split2_kernel<<<(n4w + 255) / 256, 256>>>(Wqkv, wq2, n4w);
        int n4o = D_MODEL * D_MODEL / 4;
        split2_kernel<<<(n4o + 255) / 256, 256>>>(Wout, wo2, n4o);
    }
    // 1) qkv = x @ W_qkv   (3xTF32, interleaved pre-split)
    {
        dim3 grid(QKV_N / BN, ROWS / BM);
        gemm_tf32x3_i_kernel<<<grid, 256, GEMM_SMEM_BYTES>>>(
            x2, wq2, qkv, ROWS, QKV_N, D_MODEL);
    }
    // 2) QK-LayerNorm in place
    {
        dim3 grid(ROWS, 2);
        ln_kernel<<<grid, 256>>>(qkv, qscl, kscl);
    }
    // 3) causal flash attention (3xTF32 QK, 2-term PV) -> interleaved ctx
    {
        const int smem = ATTN_SMEM_FLOATS * (int)sizeof(float);  // 89088 B
        cudaFuncSetAttribute(attn_mma_kernel,
                             cudaFuncAttributeMaxDynamicSharedMemorySize, smem);
        dim3 grid(SEQ / 64, N_HEADS, BATCH);
        attn_mma_kernel<<<grid, 128, smem>>>(qkv, c2);
    }
    // 4) out = ctx @ W_out  (3xTF32, interleaved pre-split)
    {
        dim3 grid(D_MODEL / BN, ROWS / BM);
        gemm_tf32x3_i_kernel<<<grid, 256, GEMM_SMEM_BYTES>>>(
            c2, wo2, out, ROWS, D_MODEL, D_MODEL);
    }
}

// round 12
// speedup vs baseline: 1.4609x; 1.4465x over previous
#include <cuda_runtime.h>
#include <cuda_bf16.h>
#include <math.h>
#include <cstdint>

#define D_MODEL 1024
#define N_HEADS 16
#define HD      64
#define BATCH   2
#define SEQ     2048
#define ROWS    (BATCH*SEQ)      // 4096
#define QKV_N   (3*D_MODEL)      // 3072
#define LN_EPS  1e-6f

// Scratch (device-global: no runtime allocation allowed)
__device__ float g_qkv[(size_t)ROWS * QKV_N];              // 48 MB fp32 qkv
// bf16 hi/lo planes. Activations [M][K]; weights TRANSPOSED [N][K].
__device__ __nv_bfloat16 g_xh[(size_t)ROWS * D_MODEL];
__device__ __nv_bfloat16 g_xl[(size_t)ROWS * D_MODEL];
__device__ __nv_bfloat16 g_wqh[(size_t)QKV_N * D_MODEL];   // Wqkv^T
__device__ __nv_bfloat16 g_wql[(size_t)QKV_N * D_MODEL];
__device__ __nv_bfloat16 g_woh[(size_t)D_MODEL * D_MODEL]; // Wout^T
__device__ __nv_bfloat16 g_wol[(size_t)D_MODEL * D_MODEL];
__device__ __nv_bfloat16 g_cth[(size_t)ROWS * D_MODEL];    // ctx planes
__device__ __nv_bfloat16 g_ctl[(size_t)ROWS * D_MODEL];

__device__ __forceinline__ uint32_t smem_u32(const void* p) {
    return (uint32_t)__cvta_generic_to_shared(p);
}

// ---- tf32 helpers (attention QK/PV unchanged) ----
__device__ __forceinline__ void mma_tf32(float* d, const uint32_t* a, const uint32_t* b) {
    asm volatile(
        "mma.sync.aligned.m16n8k8.row.col.f32.tf32.tf32.f32 "
        "{%0,%1,%2,%3}, {%4,%5,%6,%7}, {%8,%9}, {%0,%1,%2,%3};\n"
        : "+f"(d[0]), "+f"(d[1]), "+f"(d[2]), "+f"(d[3])
        : "r"(a[0]), "r"(a[1]), "r"(a[2]), "r"(a[3]), "r"(b[0]), "r"(b[1]));
}
__device__ __forceinline__ uint32_t cvt_tf32(float x) {
    uint32_t h;
    asm("cvt.rna.tf32.f32 %0, %1;\n" : "=r"(h) : "f"(x));
    return h;
}
__device__ __forceinline__ void split_tf32(float x, uint32_t& hi, uint32_t& lo) {
    uint32_t h = cvt_tf32(x);
    hi = h; lo = cvt_tf32(x - __uint_as_float(h));
}

// ---- bf16 helpers ----
__device__ __forceinline__ void mma_bf16(float* d, const uint32_t* a, const uint32_t* b) {
    asm volatile(
        "mma.sync.aligned.m16n8k16.row.col.f32.bf16.bf16.f32 "
        "{%0,%1,%2,%3}, {%4,%5,%6,%7}, {%8,%9}, {%0,%1,%2,%3};\n"
        : "+f"(d[0]), "+f"(d[1]), "+f"(d[2]), "+f"(d[3])
        : "r"(a[0]), "r"(a[1]), "r"(a[2]), "r"(a[3]), "r"(b[0]), "r"(b[1]));
}
__device__ __forceinline__ float bf16round(float x) {
    return __bfloat162float(__float2bfloat16_rn(x));
}
// pack bf16(a) | bf16(b)<<16
__device__ __forceinline__ uint32_t pack_bf16(float a, float b) {
    uint16_t ua = __bfloat16_as_ushort(__float2bfloat16_rn(a));
    uint16_t ub = __bfloat16_as_ushort(__float2bfloat16_rn(b));
    return (uint32_t)ua | ((uint32_t)ub << 16);
}

// ---------------------------------------------------------------------------
// Activation split: X fp32 [M][K] -> bf16 hi/lo planes. 4 elems/thread.
// ---------------------------------------------------------------------------
__global__ __launch_bounds__(256)
void xsplit_kernel(const float* __restrict__ X, __nv_bfloat16* __restrict__ Xh,
                   __nv_bfloat16* __restrict__ Xl, int n4) {
    int i = blockIdx.x * blockDim.x + threadIdx.x;
    if (i >= n4) return;
    float4 v = ((const float4*)X)[i];
    float hx = bf16round(v.x), hy = bf16round(v.y);
    float hz = bf16round(v.z), hw = bf16round(v.w);
    uint32_t* H = (uint32_t*)Xh;
    uint32_t* L = (uint32_t*)Xl;
    H[2 * i]     = pack_bf16(hx, hy);
    H[2 * i + 1] = pack_bf16(hz, hw);
    L[2 * i]     = pack_bf16(v.x - hx, v.y - hy);
    L[2 * i + 1] = pack_bf16(v.z - hz, v.w - hw);
}

// ---------------------------------------------------------------------------
// Weight transpose + split: W fp32 [Kd][Nd] -> Th/Tl bf16 [Nd][Kd].
// 32x32 tiles via smem. Block 256 threads.
// ---------------------------------------------------------------------------
__global__ __launch_bounds__(256)
void trsplit_kernel(const float* __restrict__ W, __nv_bfloat16* __restrict__ Th,
                    __nv_bfloat16* __restrict__ Tl, int Kd, int Nd) {
    __shared__ float T[32][33];
    const int tid = threadIdx.x;
    const int tx = tid & 31, ty = tid >> 5;
    const int k0 = blockIdx.y * 32, n0 = blockIdx.x * 32;
#pragma unroll
    for (int r = 0; r < 4; r++)
        T[ty + r * 8][tx] = W[(size_t)(k0 + ty + r * 8) * Nd + n0 + tx];
    __syncthreads();
#pragma unroll
    for (int i = 0; i < 2; i++) {
        int idx = tid + i * 256;           // 0..511
        int nl = idx >> 4, kp = idx & 15;
        float v0 = T[kp * 2][nl], v1 = T[kp * 2 + 1][nl];
        float h0 = bf16round(v0), h1 = bf16round(v1);
        size_t e = (size_t)(n0 + nl) * Kd + k0 + kp * 2;
        ((uint32_t*)Th)[e >> 1] = pack_bf16(h0, h1);
        ((uint32_t*)Tl)[e >> 1] = pack_bf16(v0 - h0, v1 - h1);
    }
}

// ===========================================================================
// 3xBF16 GEMM: C[M][N] = A[M][K] @ B^T where operands are pre-split bf16
// planes, A: [M][K], B: [N][K] (k-contiguous both sides -> mma row.col).
// 128x128 CTA tile, BK=32, 256 thr = 8 warps (2m x 4n), warp tile 64x32.
// m16n8k16 MMAs, 3 terms. 2-stage cp.async. Smem row stride 20 u32
// (32 bf16 data + 8 pad) -> conflict-free 32-lane LDS.32 phases.
// ===========================================================================
#define BM 128
#define BN 128
#define BKE 32                    // bf16 k per stage
#define RSTR 20                   // u32 per row
#define PLANE (128 * RSTR)        // 2560 u32
#define OFF_AL PLANE
#define OFF_BH (2 * PLANE)
#define OFF_BL (3 * PLANE)
#define STAGE_U32 (4 * PLANE)     // 10240 u32 = 40960 B
#define GEMM_SMEM_BYTES (2 * STAGE_U32 * 4)   // 81920

__global__ __launch_bounds__(256, 2)
void gemm_bf16x3_kernel(const __nv_bfloat16* __restrict__ Ah, const __nv_bfloat16* __restrict__ Al,
                        const __nv_bfloat16* __restrict__ Bh, const __nv_bfloat16* __restrict__ Bl,
                        float* __restrict__ C, int M, int N, int K) {
    extern __shared__ uint32_t smu[];

    const int tid  = threadIdx.x;
    const int lane = tid & 31;
    const int warp = tid >> 5;
    const int warp_m = warp & 1;
    const int warp_n = warp >> 1;
    const int t4  = lane >> 2;
    const int tm4 = lane & 3;
    const int bm = blockIdx.y * BM;
    const int bn = blockIdx.x * BN;

    float acc[4][4][4];
#pragma unroll
    for (int mt = 0; mt < 4; mt++)
#pragma unroll
        for (int nt = 0; nt < 4; nt++)
#pragma unroll
            for (int r = 0; r < 4; r++) acc[mt][nt][r] = 0.f;

    const int nk = K / BKE;

    auto prefetch = [&](int buf, int kt) {
        const int k0 = kt * BKE;
        const int sb = buf * STAGE_U32;
        // A planes: 128 rows x 4 chunks x 2 planes = 1024 cp.async
#pragma unroll
        for (int l = 0; l < 4; l++) {
            int c = tid + l * 256;
            int plane = c >> 9, cc = c & 511;
            int m = cc >> 2, ch = cc & 3;
            const __nv_bfloat16* src = (plane ? Al : Ah) + (size_t)(bm + m) * K + k0 + ch * 8;
            uint32_t dst = smem_u32(&smu[sb + (plane ? OFF_AL : 0) + m * RSTR + ch * 4]);
            asm volatile("cp.async.cg.shared.global [%0], [%1], 16;\n"
                         :: "r"(dst), "l"(src));
        }
        // B planes: 128 n-rows x 4 chunks x 2 planes
#pragma unroll
        for (int l = 0; l < 4; l++) {
            int c = tid + l * 256;
            int plane = c >> 9, cc = c & 511;
            int n = cc >> 2, ch = cc & 3;
            const __nv_bfloat16* src = (plane ? Bl : Bh) + (size_t)(bn + n) * K + k0 + ch * 8;
            uint32_t dst = smem_u32(&smu[sb + (plane ? OFF_BL : OFF_BH) + n * RSTR + ch * 4]);
            asm volatile("cp.async.cg.shared.global [%0], [%1], 16;\n"
                         :: "r"(dst), "l"(src));
        }
        asm volatile("cp.async.commit_group;\n");
    };

    prefetch(0, 0);

    for (int kt = 0; kt < nk; kt++) {
        const int buf = kt & 1;
        if (kt + 1 < nk) {
            prefetch(buf ^ 1, kt + 1);
            asm volatile("cp.async.wait_group 1;\n");
        } else {
            asm volatile("cp.async.wait_group 0;\n");
        }
        __syncthreads();

        const uint32_t* AhU = smu + buf * STAGE_U32;
        const uint32_t* AlU = AhU + OFF_AL;
        const uint32_t* BhU = AhU + OFF_BH;
        const uint32_t* BlU = AhU + OFF_BL;

#pragma unroll
        for (int ks = 0; ks < 2; ks++) {
            const int k0u = ks * 8;       // 16 bf16 = 8 u32 per k-step
            uint32_t ah[4][4], al[4][4];
#pragma unroll
            for (int mt = 0; mt < 4; mt++) {
                const int rb = warp_m * 64 + mt * 16;
                const int i0 = (rb + t4)     * RSTR + k0u + tm4;
                const int i1 = (rb + 8 + t4) * RSTR + k0u + tm4;
                ah[mt][0] = AhU[i0];     al[mt][0] = AlU[i0];
                ah[mt][1] = AhU[i1];     al[mt][1] = AlU[i1];
                ah[mt][2] = AhU[i0 + 4]; al[mt][2] = AlU[i0 + 4];
                ah[mt][3] = AhU[i1 + 4]; al[mt][3] = AlU[i1 + 4];
            }
            uint32_t bh[4][2], bl[4][2];
#pragma unroll
            for (int nt = 0; nt < 4; nt++) {
                const int nb = warp_n * 32 + nt * 8;
                const int i0 = (nb + t4) * RSTR + k0u + tm4;
                bh[nt][0] = BhU[i0];     bl[nt][0] = BlU[i0];
                bh[nt][1] = BhU[i0 + 4]; bl[nt][1] = BlU[i0 + 4];
            }
#pragma unroll
            for (int mt = 0; mt < 4; mt++)
#pragma unroll
                for (int nt = 0; nt < 4; nt++) {
                    mma_bf16(acc[mt][nt], al[mt], bh[nt]);
                    mma_bf16(acc[mt][nt], ah[mt], bl[nt]);
                    mma_bf16(acc[mt][nt], ah[mt], bh[nt]);
                }
        }
        __syncthreads();
    }

#pragma unroll
    for (int mt = 0; mt < 4; mt++) {
#pragma unroll
        for (int nt = 0; nt < 4; nt++) {
            const int row = bm + warp_m * 64 + mt * 16 + t4;
            const int col = bn + warp_n * 32 + nt * 8 + tm4 * 2;
            float2 v0 = make_float2(acc[mt][nt][0], acc[mt][nt][1]);
            float2 v1 = make_float2(acc[mt][nt][2], acc[mt][nt][3]);
            *(float2*)&C[(size_t)row * N + col]       = v0;
            *(float2*)&C[(size_t)(row + 8) * N + col] = v1;
        }
    }
}

// ---------------------------------------------------------------------------
// LayerNorm over last dim (1024), scale-only, in-place on q/k slices of qkv.
// ---------------------------------------------------------------------------
__global__ __launch_bounds__(256)
void ln_kernel(float* __restrict__ qkv, const float* __restrict__ q_scale,
               const float* __restrict__ k_scale) {
    const int row = blockIdx.x;
    const int which = blockIdx.y;
    const float* scale = which ? k_scale : q_scale;
    float* ptr = qkv + (size_t)row * QKV_N + which * D_MODEL;

    const int tid = threadIdx.x;
    float v[4];
    float sum = 0.f, sq = 0.f;
#pragma unroll
    for (int i = 0; i < 4; i++) {
        v[i] = ptr[tid + i * 256];
        sum += v[i];
        sq += v[i] * v[i];
    }
#pragma unroll
    for (int o = 16; o > 0; o >>= 1) {
        sum += __shfl_xor_sync(0xffffffffu, sum, o);
        sq  += __shfl_xor_sync(0xffffffffu, sq,  o);
    }
    __shared__ float ssum[8], ssq[8];
    const int warp = tid >> 5, lane = tid & 31;
    if (lane == 0) { ssum[warp] = sum; ssq[warp] = sq; }
    __syncthreads();
    if (tid == 0) {
        float a = 0.f, b = 0.f;
#pragma unroll
        for (int w = 0; w < 8; w++) { a += ssum[w]; b += ssq[w]; }
        ssum[0] = a; ssq[0] = b;
    }
    __syncthreads();
    const float mean = ssum[0] * (1.f / D_MODEL);
    const float var  = ssq[0] * (1.f / D_MODEL) - mean * mean;
    const float inv  = rsqrtf(var + LN_EPS);
#pragma unroll
    for (int i = 0; i < 4; i++) {
        int c = tid + i * 256;
        ptr[c] = (v[i] - mean) * inv * scale[c];
    }
}

// ===========================================================================
// Flash attention (3xTF32 QK^T, 2-term PV with P=tf32-hi). Causal.
// Epilogue writes bf16 hi/lo ctx planes for the bf16x3 out-proj.
// ===========================================================================
#define QP_STR 68
#define K_STR  68
#define V_STR  72
#define ATTN_SMEM_FLOATS 22272   // 89088 B

__global__ __launch_bounds__(128)
void attn_mma_kernel(const float* __restrict__ qkv,
                     __nv_bfloat16* __restrict__ ctxh, __nv_bfloat16* __restrict__ ctxl) {
    extern __shared__ float sm[];
    float* QPs = sm;                 // Q tile, later P tile
    float* Ksm = sm + 4352;          // 2 buffers of 64*68
    float* Vsm = sm + 13056;         // 2 buffers of 64*72

    const int qt = blockIdx.x;
    const int h  = blockIdx.y;
    const int b  = blockIdx.z;
    const int tid  = threadIdx.x;
    const int lane = tid & 31;
    const int w    = tid >> 5;
    const int t4   = lane >> 2;
    const int tm4  = lane & 3;
    const int w16  = w * 16;

    const float* qbase = qkv + ((size_t)(b * SEQ + qt * 64)) * QKV_N + (size_t)h * HD;

    auto prefetch_kv = [&](int buf, int kt) {
        const float* kb = qkv + ((size_t)(b * SEQ + kt * 64)) * QKV_N + D_MODEL + (size_t)h * HD;
        const float* vb = kb + D_MODEL;
        float* Kd = Ksm + buf * (64 * K_STR);
        float* Vd = Vsm + buf * (64 * V_STR);
#pragma unroll
        for (int l = 0; l < 8; l++) {
            int c = tid + l * 128;
            int row = c >> 4, c4 = c & 15;
            const float* srcK = kb + (size_t)row * QKV_N + c4 * 4;
            uint32_t dstK = smem_u32(&Kd[row * K_STR + c4 * 4]);
            asm volatile("cp.async.cg.shared.global [%0], [%1], 16;\n"
                         :: "r"(dstK), "l"(srcK));
            const float* srcV = vb + (size_t)row * QKV_N + c4 * 4;
            uint32_t dstV = smem_u32(&Vd[row * V_STR + c4 * 4]);
            asm volatile("cp.async.cg.shared.global [%0], [%1], 16;\n"
                         :: "r"(dstV), "l"(srcV));
        }
        asm volatile("cp.async.commit_group;\n");
    };

    prefetch_kv(0, 0);
#pragma unroll
    for (int l = 0; l < 8; l++) {
        int c = tid + l * 128;
        int row = c >> 4, c4 = c & 15;
        float4 v = *(const float4*)(qbase + (size_t)row * QKV_N + c4 * 4);
        *(float4*)&QPs[row * QP_STR + c4 * 4] = v;
    }
    __syncthreads();

    uint32_t qah[8][4], qal[8][4];
#pragma unroll
    for (int ks = 0; ks < 8; ks++) {
        const int k0 = ks * 8;
        float v0 = 0.125f * QPs[(w16 + t4)     * QP_STR + k0 + tm4];
        float v1 = 0.125f * QPs[(w16 + t4 + 8) * QP_STR + k0 + tm4];
        float v2 = 0.125f * QPs[(w16 + t4)     * QP_STR + k0 + tm4 + 4];
        float v3 = 0.125f * QPs[(w16 + t4 + 8) * QP_STR + k0 + tm4 + 4];
        split_tf32(v0, qah[ks][0], qal[ks][0]);
        split_tf32(v1, qah[ks][1], qal[ks][1]);
        split_tf32(v2, qah[ks][2], qal[ks][2]);
        split_tf32(v3, qah[ks][3], qal[ks][3]);
    }
    __syncthreads();

    float m0 = -1e30f, m1 = -1e30f, l0 = 0.f, l1 = 0.f;
    float oacc[8][4];
#pragma unroll
    for (int nt = 0; nt < 8; nt++)
#pragma unroll
        for (int r = 0; r < 4; r++) oacc[nt][r] = 0.f;

    for (int kt = 0; kt <= qt; kt++) {
        const int buf = kt & 1;
        asm volatile("cp.async.wait_group 0;\n");
        __syncthreads();
        if (kt < qt) prefetch_kv(buf ^ 1, kt + 1);

        const float* Kb = Ksm + buf * (64 * K_STR);
        const float* Vb = Vsm + buf * (64 * V_STR);

        float s[8][4];
#pragma unroll
        for (int nt = 0; nt < 8; nt++)
#pragma unroll
            for (int r = 0; r < 4; r++) s[nt][r] = 0.f;

#pragma unroll
        for (int ks = 0; ks < 8; ks++) {
            const int k0 = ks * 8;
            uint32_t kh[8][2], kl[8][2];
#pragma unroll
            for (int nt = 0; nt < 8; nt++) {
                float v0 = Kb[(nt * 8 + t4) * K_STR + k0 + tm4];
                float v1 = Kb[(nt * 8 + t4) * K_STR + k0 + tm4 + 4];
                split_tf32(v0, kh[nt][0], kl[nt][0]);
                split_tf32(v1, kh[nt][1], kl[nt][1]);
            }
#pragma unroll
            for (int nt = 0; nt < 8; nt++) {
                mma_tf32(s[nt], qal[ks], kh[nt]);
                mma_tf32(s[nt], qah[ks], kl[nt]);
                mma_tf32(s[nt], qah[ks], kh[nt]);
            }
        }

        if (kt == qt) {
#pragma unroll
            for (int nt = 0; nt < 8; nt++) {
                const int c0 = nt * 8 + tm4 * 2;
                const int r0 = w16 + t4;
                if (c0     > r0)     s[nt][0] = -1e30f;
                if (c0 + 1 > r0)     s[nt][1] = -1e30f;
                if (c0     > r0 + 8) s[nt][2] = -1e30f;
                if (c0 + 1 > r0 + 8) s[nt][3] = -1e30f;
            }
        }

        float rm0 = -1e30f, rm1 = -1e30f;
#pragma unroll
        for (int nt = 0; nt < 8; nt++) {
            rm0 = fmaxf(rm0, fmaxf(s[nt][0], s[nt][1]));
            rm1 = fmaxf(rm1, fmaxf(s[nt][2], s[nt][3]));
        }
#pragma unroll
        for (int o = 1; o <= 2; o <<= 1) {
            rm0 = fmaxf(rm0, __shfl_xor_sync(0xffffffffu, rm0, o));
            rm1 = fmaxf(rm1, __shfl_xor_sync(0xffffffffu, rm1, o));
        }
        const float nm0 = fmaxf(m0, rm0);
        const float nm1 = fmaxf(m1, rm1);
        const float c0 = expf(m0 - nm0);
        const float c1 = expf(m1 - nm1);
        float rs0 = 0.f, rs1 = 0.f;
#pragma unroll
        for (int nt = 0; nt < 8; nt++) {
            s[nt][0] = expf(s[nt][0] - nm0);
            s[nt][1] = expf(s[nt][1] - nm0);
            s[nt][2] = expf(s[nt][2] - nm1);
            s[nt][3] = expf(s[nt][3] - nm1);
            rs0 += s[nt][0] + s[nt][1];
            rs1 += s[nt][2] + s[nt][3];
        }
#pragma unroll
        for (int o = 1; o <= 2; o <<= 1) {
            rs0 += __shfl_xor_sync(0xffffffffu, rs0, o);
            rs1 += __shfl_xor_sync(0xffffffffu, rs1, o);
        }
        l0 = l0 * c0 + rs0;  m0 = nm0;
        l1 = l1 * c1 + rs1;  m1 = nm1;
#pragma unroll
        for (int nt = 0; nt < 8; nt++) {
            oacc[nt][0] *= c0; oacc[nt][1] *= c0;
            oacc[nt][2] *= c1; oacc[nt][3] *= c1;
        }

#pragma unroll
        for (int nt = 0; nt < 8; nt++) {
            *(float2*)&QPs[(w16 + t4)     * QP_STR + nt * 8 + tm4 * 2] =
                make_float2(s[nt][0], s[nt][1]);
            *(float2*)&QPs[(w16 + t4 + 8) * QP_STR + nt * 8 + tm4 * 2] =
                make_float2(s[nt][2], s[nt][3]);
        }
        __syncwarp();

        // ---- O += P @ V : P tf32-hi only, V split -> 2 MMAs ----
#pragma unroll
        for (int ks = 0; ks < 8; ks++) {
            const int k0 = ks * 8;
            uint32_t pah[4];
            pah[0] = cvt_tf32(QPs[(w16 + t4)     * QP_STR + k0 + tm4]);
            pah[1] = cvt_tf32(QPs[(w16 + t4 + 8) * QP_STR + k0 + tm4]);
            pah[2] = cvt_tf32(QPs[(w16 + t4)     * QP_STR + k0 + tm4 + 4]);
            pah[3] = cvt_tf32(QPs[(w16 + t4 + 8) * QP_STR + k0 + tm4 + 4]);
#pragma unroll
            for (int nt = 0; nt < 8; nt++) {
                uint32_t vh[2], vl[2];
                float v0 = Vb[(k0 + tm4)     * V_STR + nt * 8 + t4];
                float v1 = Vb[(k0 + tm4 + 4) * V_STR + nt * 8 + t4];
                split_tf32(v0, vh[0], vl[0]);
                split_tf32(v1, vh[1], vl[1]);
                mma_tf32(oacc[nt], pah, vl);
                mma_tf32(oacc[nt], pah, vh);
            }
        }
        __syncwarp();
    }

    // epilogue: normalize, split to bf16 hi/lo planes
    const float i0 = 1.f / l0, i1 = 1.f / l1;
    const size_t r0 = (size_t)(b * SEQ + qt * 64 + w16 + t4) * D_MODEL;
    const size_t r1 = (size_t)(b * SEQ + qt * 64 + w16 + t4 + 8) * D_MODEL;
#pragma unroll
    for (int nt = 0; nt < 8; nt++) {
        const int col = h * HD + nt * 8 + tm4 * 2;
        float o00 = oacc[nt][0] * i0, o01 = oacc[nt][1] * i0;
        float o10 = oacc[nt][2] * i1, o11 = oacc[nt][3] * i1;
        float h00 = bf16round(o00), h01 = bf16round(o01);
        float h10 = bf16round(o10), h11 = bf16round(o11);
        ((uint32_t*)ctxh)[(r0 + col) >> 1] = pack_bf16(h00, h01);
        ((uint32_t*)ctxl)[(r0 + col) >> 1] = pack_bf16(o00 - h00, o01 - h01);
        ((uint32_t*)ctxh)[(r1 + col) >> 1] = pack_bf16(h10, h11);
        ((uint32_t*)ctxl)[(r1 + col) >> 1] = pack_bf16(o10 - h10, o11 - h11);
    }
}

// ---------------------------------------------------------------------------
extern "C" void kernel_launch(void* const* d_in, const int* in_sizes, int n_in,
                              void* d_out, int out_size) {
    const float* x     = (const float*)d_in[0];
    const float* Wqkv  = (const float*)d_in[1];
    const float* qscl  = (const float*)d_in[2];
    const float* kscl  = (const float*)d_in[3];
    const float* Wout  = (const float*)d_in[4];
    float* out = (float*)d_out;

    float* qkv;
    __nv_bfloat16 *xh, *xl, *wqh, *wql, *woh, *wol, *cth, *ctl;
    cudaGetSymbolAddress((void**)&qkv, g_qkv);
    cudaGetSymbolAddress((void**)&xh,  g_xh);
    cudaGetSymbolAddress((void**)&xl,  g_xl);
    cudaGetSymbolAddress((void**)&wqh, g_wqh);
    cudaGetSymbolAddress((void**)&wql, g_wql);
    cudaGetSymbolAddress((void**)&woh, g_woh);
    cudaGetSymbolAddress((void**)&wol, g_wol);
    cudaGetSymbolAddress((void**)&cth, g_cth);
    cudaGetSymbolAddress((void**)&ctl, g_ctl);

    cudaFuncSetAttribute(gemm_bf16x3_kernel,
                         cudaFuncAttributeMaxDynamicSharedMemorySize, GEMM_SMEM_BYTES);

    // 0) splits: x elementwise; weights transpose+split to [N][K]
    {
        int n4x = ROWS * D_MODEL / 4;
        xsplit_kernel<<<(n4x + 255) / 256, 256>>>(x, xh, xl, n4x);
        dim3 gq(QKV_N / 32, D_MODEL / 32);
        trsplit_kernel<<<gq, 256>>>(Wqkv, wqh, wql, D_MODEL, QKV_N);
        dim3 go(D_MODEL / 32, D_MODEL / 32);
        trsplit_kernel<<<go, 256>>>(Wout, woh, wol, D_MODEL, D_MODEL);
    }
    // 1) qkv = x @ W_qkv   (3xBF16)
    {
        dim3 grid(QKV_N / BN, ROWS / BM);
        gemm_bf16x3_kernel<<<grid, 256, GEMM_SMEM_BYTES>>>(
            xh, xl, wqh, wql, qkv, ROWS, QKV_N, D_MODEL);
    }
    // 2) QK-LayerNorm in place
    {
        dim3 grid(ROWS, 2);
        ln_kernel<<<grid, 256>>>(qkv, qscl, kscl);
    }
    // 3) causal flash attention -> bf16 hi/lo ctx planes
    {
        const int smem = ATTN_SMEM_FLOATS * (int)sizeof(float);  // 89088 B
        cudaFuncSetAttribute(attn_mma_kernel,
                             cudaFuncAttributeMaxDynamicSharedMemorySize, smem);
        dim3 grid(SEQ / 64, N_HEADS, BATCH);
        attn_mma_kernel<<<grid, 128, smem>>>(qkv, cth, ctl);
    }
    // 4) out = ctx @ W_out  (3xBF16)
    {
        dim3 grid(D_MODEL / BN, ROWS / BM);
        gemm_bf16x3_kernel<<<grid, 256, GEMM_SMEM_BYTES>>>(
            cth, ctl, woh, wol, out, ROWS, D_MODEL, D_MODEL);
    }
}

// round 14
// speedup vs baseline: 2.0243x; 1.3857x over previous
#include <cuda_runtime.h>
#include <cuda_bf16.h>
#include <math.h>
#include <cstdint>

#define D_MODEL 1024
#define N_HEADS 16
#define HD      64
#define BATCH   2
#define SEQ     2048
#define ROWS    (BATCH*SEQ)      // 4096
#define QKV_N   (3*D_MODEL)      // 3072
#define LN_EPS  1e-6f

// Scratch (device-global: no runtime allocation allowed)
__device__ float g_qkv[(size_t)ROWS * QKV_N];              // 48 MB fp32 qkv
// bf16 hi/lo planes for GEMMs. Activations [M][K]; weights TRANSPOSED [N][K].
__device__ __nv_bfloat16 g_xh[(size_t)ROWS * D_MODEL];
__device__ __nv_bfloat16 g_xl[(size_t)ROWS * D_MODEL];
__device__ __nv_bfloat16 g_wqh[(size_t)QKV_N * D_MODEL];
__device__ __nv_bfloat16 g_wql[(size_t)QKV_N * D_MODEL];
__device__ __nv_bfloat16 g_woh[(size_t)D_MODEL * D_MODEL];
__device__ __nv_bfloat16 g_wol[(size_t)D_MODEL * D_MODEL];
__device__ __nv_bfloat16 g_cth[(size_t)ROWS * D_MODEL];    // ctx planes
__device__ __nv_bfloat16 g_ctl[(size_t)ROWS * D_MODEL];
// attention operand planes (bf16, packed as u32 pairs)
__device__ uint32_t g_kph[(size_t)ROWS * D_MODEL / 2];     // K post-LN hi
__device__ uint32_t g_kpl[(size_t)ROWS * D_MODEL / 2];     // K post-LN lo
__device__ uint32_t g_vth[(size_t)ROWS * D_MODEL / 2];     // V^T hi  [b,h][d][s]
__device__ uint32_t g_vtl[(size_t)ROWS * D_MODEL / 2];     // V^T lo

__device__ __forceinline__ uint32_t smem_u32(const void* p) {
    return (uint32_t)__cvta_generic_to_shared(p);
}

__device__ __forceinline__ void mma_bf16(float* d, const uint32_t* a, const uint32_t* b) {
    asm volatile(
        "mma.sync.aligned.m16n8k16.row.col.f32.bf16.bf16.f32 "
        "{%0,%1,%2,%3}, {%4,%5,%6,%7}, {%8,%9}, {%0,%1,%2,%3};\n"
        : "+f"(d[0]), "+f"(d[1]), "+f"(d[2]), "+f"(d[3])
        : "r"(a[0]), "r"(a[1]), "r"(a[2]), "r"(a[3]), "r"(b[0]), "r"(b[1]));
}
__device__ __forceinline__ float bf16round(float x) {
    return __bfloat162float(__float2bfloat16_rn(x));
}
__device__ __forceinline__ uint32_t pack_bf16(float a, float b) {
    uint16_t ua = __bfloat16_as_ushort(__float2bfloat16_rn(a));
    uint16_t ub = __bfloat16_as_ushort(__float2bfloat16_rn(b));
    return (uint32_t)ua | ((uint32_t)ub << 16);
}

// ---------------------------------------------------------------------------
// Activation split: X fp32 [M][K] -> bf16 hi/lo planes. 4 elems/thread.
// ---------------------------------------------------------------------------
__global__ __launch_bounds__(256)
void xsplit_kernel(const float* __restrict__ X, __nv_bfloat16* __restrict__ Xh,
                   __nv_bfloat16* __restrict__ Xl, int n4) {
    int i = blockIdx.x * blockDim.x + threadIdx.x;
    if (i >= n4) return;
    float4 v = ((const float4*)X)[i];
    float hx = bf16round(v.x), hy = bf16round(v.y);
    float hz = bf16round(v.z), hw = bf16round(v.w);
    uint32_t* H = (uint32_t*)Xh;
    uint32_t* L = (uint32_t*)Xl;
    H[2 * i]     = pack_bf16(hx, hy);
    H[2 * i + 1] = pack_bf16(hz, hw);
    L[2 * i]     = pack_bf16(v.x - hx, v.y - hy);
    L[2 * i + 1] = pack_bf16(v.z - hz, v.w - hw);
}

// ---------------------------------------------------------------------------
// Weight transpose + split: W fp32 [Kd][Nd] -> Th/Tl bf16 [Nd][Kd].
// ---------------------------------------------------------------------------
__global__ __launch_bounds__(256)
void trsplit_kernel(const float* __restrict__ W, __nv_bfloat16* __restrict__ Th,
                    __nv_bfloat16* __restrict__ Tl, int Kd, int Nd) {
    __shared__ float T[32][33];
    const int tid = threadIdx.x;
    const int tx = tid & 31, ty = tid >> 5;
    const int k0 = blockIdx.y * 32, n0 = blockIdx.x * 32;
#pragma unroll
    for (int r = 0; r < 4; r++)
        T[ty + r * 8][tx] = W[(size_t)(k0 + ty + r * 8) * Nd + n0 + tx];
    __syncthreads();
#pragma unroll
    for (int i = 0; i < 2; i++) {
        int idx = tid + i * 256;
        int nl = idx >> 4, kp = idx & 15;
        float v0 = T[kp * 2][nl], v1 = T[kp * 2 + 1][nl];
        float h0 = bf16round(v0), h1 = bf16round(v1);
        size_t e = (size_t)(n0 + nl) * Kd + k0 + kp * 2;
        ((uint32_t*)Th)[e >> 1] = pack_bf16(h0, h1);
        ((uint32_t*)Tl)[e >> 1] = pack_bf16(v0 - h0, v1 - h1);
    }
}

// ---------------------------------------------------------------------------
// V transpose + split: qkv v-slice -> VT planes [(b*16+h)*64+d][s] bf16 hi/lo.
// ---------------------------------------------------------------------------
__global__ __launch_bounds__(256)
void vtsplit_kernel(const float* __restrict__ qkv,
                    uint32_t* __restrict__ VTh, uint32_t* __restrict__ VTl) {
    __shared__ float T[32][33];
    const int tid = threadIdx.x;
    const int s0 = blockIdx.x * 32;
    const int d0 = blockIdx.y * 32;
    const int bh = blockIdx.z;
    const int b  = bh / N_HEADS;
    const int h  = bh % N_HEADS;
    const int tx = tid & 31, ty = tid >> 5;
#pragma unroll
    for (int r = 0; r < 4; r++) {
        int si = ty + r * 8;
        T[si][tx] = qkv[((size_t)(b * SEQ + s0 + si)) * QKV_N + 2 * D_MODEL + h * HD + d0 + tx];
    }
    __syncthreads();
#pragma unroll
    for (int i = 0; i < 2; i++) {
        int idx = tid + i * 256;           // 0..511
        int dl = idx >> 4, sp = idx & 15;
        float v0 = T[sp * 2][dl], v1 = T[sp * 2 + 1][dl];
        float h0 = bf16round(v0), h1 = bf16round(v1);
        size_t u = (size_t)(bh * HD + d0 + dl) * (SEQ / 2) + (s0 >> 1) + sp;
        VTh[u] = pack_bf16(h0, h1);
        VTl[u] = pack_bf16(v0 - h0, v1 - h1);
    }
}

// ===========================================================================
// 3xBF16 GEMM (validated R11): C[M][N] = A[M][K] @ B^T, pre-split planes.
// ===========================================================================
#define BM 128
#define BN 128
#define BKE 32
#define RSTR 20
#define PLANE (128 * RSTR)
#define OFF_AL PLANE
#define OFF_BH (2 * PLANE)
#define OFF_BL (3 * PLANE)
#define STAGE_U32 (4 * PLANE)
#define GEMM_SMEM_BYTES (2 * STAGE_U32 * 4)   // 81920

__global__ __launch_bounds__(256, 2)
void gemm_bf16x3_kernel(const __nv_bfloat16* __restrict__ Ah, const __nv_bfloat16* __restrict__ Al,
                        const __nv_bfloat16* __restrict__ Bh, const __nv_bfloat16* __restrict__ Bl,
                        float* __restrict__ C, int M, int N, int K) {
    extern __shared__ uint32_t smu[];

    const int tid  = threadIdx.x;
    const int lane = tid & 31;
    const int warp = tid >> 5;
    const int warp_m = warp & 1;
    const int warp_n = warp >> 1;
    const int t4  = lane >> 2;
    const int tm4 = lane & 3;
    const int bm = blockIdx.y * BM;
    const int bn = blockIdx.x * BN;

    float acc[4][4][4];
#pragma unroll
    for (int mt = 0; mt < 4; mt++)
#pragma unroll
        for (int nt = 0; nt < 4; nt++)
#pragma unroll
            for (int r = 0; r < 4; r++) acc[mt][nt][r] = 0.f;

    const int nk = K / BKE;

    auto prefetch = [&](int buf, int kt) {
        const int k0 = kt * BKE;
        const int sb = buf * STAGE_U32;
#pragma unroll
        for (int l = 0; l < 4; l++) {
            int c = tid + l * 256;
            int plane = c >> 9, cc = c & 511;
            int m = cc >> 2, ch = cc & 3;
            const __nv_bfloat16* src = (plane ? Al : Ah) + (size_t)(bm + m) * K + k0 + ch * 8;
            uint32_t dst = smem_u32(&smu[sb + (plane ? OFF_AL : 0) + m * RSTR + ch * 4]);
            asm volatile("cp.async.cg.shared.global [%0], [%1], 16;\n"
                         :: "r"(dst), "l"(src));
        }
#pragma unroll
        for (int l = 0; l < 4; l++) {
            int c = tid + l * 256;
            int plane = c >> 9, cc = c & 511;
            int n = cc >> 2, ch = cc & 3;
            const __nv_bfloat16* src = (plane ? Bl : Bh) + (size_t)(bn + n) * K + k0 + ch * 8;
            uint32_t dst = smem_u32(&smu[sb + (plane ? OFF_BL : OFF_BH) + n * RSTR + ch * 4]);
            asm volatile("cp.async.cg.shared.global [%0], [%1], 16;\n"
                         :: "r"(dst), "l"(src));
        }
        asm volatile("cp.async.commit_group;\n");
    };

    prefetch(0, 0);

    for (int kt = 0; kt < nk; kt++) {
        const int buf = kt & 1;
        if (kt + 1 < nk) {
            prefetch(buf ^ 1, kt + 1);
            asm volatile("cp.async.wait_group 1;\n");
        } else {
            asm volatile("cp.async.wait_group 0;\n");
        }
        __syncthreads();

        const uint32_t* AhU = smu + buf * STAGE_U32;
        const uint32_t* AlU = AhU + OFF_AL;
        const uint32_t* BhU = AhU + OFF_BH;
        const uint32_t* BlU = AhU + OFF_BL;

#pragma unroll
        for (int ks = 0; ks < 2; ks++) {
            const int k0u = ks * 8;
            uint32_t ah[4][4], al[4][4];
#pragma unroll
            for (int mt = 0; mt < 4; mt++) {
                const int rb = warp_m * 64 + mt * 16;
                const int i0 = (rb + t4)     * RSTR + k0u + tm4;
                const int i1 = (rb + 8 + t4) * RSTR + k0u + tm4;
                ah[mt][0] = AhU[i0];     al[mt][0] = AlU[i0];
                ah[mt][1] = AhU[i1];     al[mt][1] = AlU[i1];
                ah[mt][2] = AhU[i0 + 4]; al[mt][2] = AlU[i0 + 4];
                ah[mt][3] = AhU[i1 + 4]; al[mt][3] = AlU[i1 + 4];
            }
            uint32_t bh[4][2], bl[4][2];
#pragma unroll
            for (int nt = 0; nt < 4; nt++) {
                const int nb = warp_n * 32 + nt * 8;
                const int i0 = (nb + t4) * RSTR + k0u + tm4;
                bh[nt][0] = BhU[i0];     bl[nt][0] = BlU[i0];
                bh[nt][1] = BhU[i0 + 4]; bl[nt][1] = BlU[i0 + 4];
            }
#pragma unroll
            for (int mt = 0; mt < 4; mt++)
#pragma unroll
                for (int nt = 0; nt < 4; nt++) {
                    mma_bf16(acc[mt][nt], al[mt], bh[nt]);
                    mma_bf16(acc[mt][nt], ah[mt], bl[nt]);
                    mma_bf16(acc[mt][nt], ah[mt], bh[nt]);
                }
        }
        __syncthreads();
    }

#pragma unroll
    for (int mt = 0; mt < 4; mt++) {
#pragma unroll
        for (int nt = 0; nt < 4; nt++) {
            const int row = bm + warp_m * 64 + mt * 16 + t4;
            const int col = bn + warp_n * 32 + nt * 8 + tm4 * 2;
            float2 v0 = make_float2(acc[mt][nt][0], acc[mt][nt][1]);
            float2 v1 = make_float2(acc[mt][nt][2], acc[mt][nt][3]);
            *(float2*)&C[(size_t)row * N + col]       = v0;
            *(float2*)&C[(size_t)(row + 8) * N + col] = v1;
        }
    }
}

// ---------------------------------------------------------------------------
// LayerNorm (scale-only). which=0: q normalized fp32 in place.
// which=1: k -> pre-split bf16 hi/lo planes (u32 packed).
// ---------------------------------------------------------------------------
__global__ __launch_bounds__(256)
void ln_kernel(float* __restrict__ qkv, const float* __restrict__ q_scale,
               const float* __restrict__ k_scale,
               uint32_t* __restrict__ kh, uint32_t* __restrict__ kl) {
    const int row = blockIdx.x;
    const int which = blockIdx.y;
    const float* scale = which ? k_scale : q_scale;
    float* ptr = qkv + (size_t)row * QKV_N + which * D_MODEL;

    const int tid = threadIdx.x;
    float4 v = ((const float4*)ptr)[tid];
    float sum = v.x + v.y + v.z + v.w;
    float sq  = v.x * v.x + v.y * v.y + v.z * v.z + v.w * v.w;
#pragma unroll
    for (int o = 16; o > 0; o >>= 1) {
        sum += __shfl_xor_sync(0xffffffffu, sum, o);
        sq  += __shfl_xor_sync(0xffffffffu, sq,  o);
    }
    __shared__ float ssum[8], ssq[8];
    const int warp = tid >> 5, lane = tid & 31;
    if (lane == 0) { ssum[warp] = sum; ssq[warp] = sq; }
    __syncthreads();
    if (tid == 0) {
        float a = 0.f, bsum = 0.f;
#pragma unroll
        for (int w = 0; w < 8; w++) { a += ssum[w]; bsum += ssq[w]; }
        ssum[0] = a; ssq[0] = bsum;
    }
    __syncthreads();
    const float mean = ssum[0] * (1.f / D_MODEL);
    const float var  = ssq[0] * (1.f / D_MODEL) - mean * mean;
    const float inv  = rsqrtf(var + LN_EPS);

    const int c = tid * 4;
    float n0 = (v.x - mean) * inv * scale[c];
    float n1 = (v.y - mean) * inv * scale[c + 1];
    float n2 = (v.z - mean) * inv * scale[c + 2];
    float n3 = (v.w - mean) * inv * scale[c + 3];
    if (which == 0) {
        ((float4*)ptr)[tid] = make_float4(n0, n1, n2, n3);
    } else {
        float h0 = bf16round(n0), h1 = bf16round(n1);
        float h2 = bf16round(n2), h3 = bf16round(n3);
        size_t u = (size_t)row * (D_MODEL / 2) + tid * 2;
        kh[u]     = pack_bf16(h0, h1);
        kh[u + 1] = pack_bf16(h2, h3);
        kl[u]     = pack_bf16(n0 - h0, n1 - h1);
        kl[u + 1] = pack_bf16(n2 - h2, n3 - h3);
    }
}

// ===========================================================================
// Flash attention, all-bf16x3 tensor core. Causal. 128 thr = 4 warps.
// ===========================================================================
#define KSTR 36                   // u32 per 64-bf16 row (+4 pad)
#define APLANE (64 * KSTR)        // 2304 u32
#define OFF_K  4608
#define OFF_VT 13824
#define ATTN_SMEM_BYTES (23040 * 4)   // 92160

__global__ __launch_bounds__(128)
void attn_bf16_kernel(const float* __restrict__ qkv,
                      const uint32_t* __restrict__ Kh, const uint32_t* __restrict__ Kl,
                      const uint32_t* __restrict__ VTh, const uint32_t* __restrict__ VTl,
                      __nv_bfloat16* __restrict__ ctxh, __nv_bfloat16* __restrict__ ctxl) {
    extern __shared__ uint32_t smu[];
    uint32_t* Ph = smu;
    uint32_t* Pl = smu + APLANE;

    const int qt = blockIdx.x;
    const int h  = blockIdx.y;
    const int b  = blockIdx.z;
    const int tid  = threadIdx.x;
    const int lane = tid & 31;
    const int w    = tid >> 5;
    const int t4   = lane >> 2;
    const int tm4  = lane & 3;
    const int w16  = w * 16;

    auto prefetch_kv = [&](int buf, int kt) {
        const size_t kgo = ((size_t)(b * SEQ + kt * 64) * D_MODEL + h * HD) / 2;
        const size_t vgo = ((size_t)((b * N_HEADS + h) * HD) * SEQ + (size_t)kt * 64) / 2;
        uint32_t* kd = smu + OFF_K + buf * 2 * APLANE;
        uint32_t* vd = smu + OFF_VT + buf * 2 * APLANE;
#pragma unroll
        for (int l = 0; l < 4; l++) {
            int c = tid + l * 128;          // 0..511
            int row = c >> 3, ch = c & 7;
            asm volatile("cp.async.cg.shared.global [%0], [%1], 16;\n"
                :: "r"(smem_u32(&kd[row * KSTR + ch * 4])), "l"(Kh + kgo + (size_t)row * 512 + ch * 4));
            asm volatile("cp.async.cg.shared.global [%0], [%1], 16;\n"
                :: "r"(smem_u32(&kd[APLANE + row * KSTR + ch * 4])), "l"(Kl + kgo + (size_t)row * 512 + ch * 4));
            asm volatile("cp.async.cg.shared.global [%0], [%1], 16;\n"
                :: "r"(smem_u32(&vd[row * KSTR + ch * 4])), "l"(VTh + vgo + (size_t)row * 1024 + ch * 4));
            asm volatile("cp.async.cg.shared.global [%0], [%1], 16;\n"
                :: "r"(smem_u32(&vd[APLANE + row * KSTR + ch * 4])), "l"(VTl + vgo + (size_t)row * 1024 + ch * 4));
        }
        asm volatile("cp.async.commit_group;\n");
    };

    prefetch_kv(0, 0);

    // stage Q fp32 in the P area (stride 68 floats), then build register frags
    {
        float* Qs = (float*)smu;
        const float* qbase = qkv + ((size_t)(b * SEQ + qt * 64)) * QKV_N + (size_t)h * HD;
#pragma unroll
        for (int l = 0; l < 8; l++) {
            int c = tid + l * 128;
            int row = c >> 4, c4 = c & 15;
            float4 v = *(const float4*)(qbase + (size_t)row * QKV_N + c4 * 4);
            *(float4*)&Qs[row * 68 + c4 * 4] = v;
        }
    }
    __syncthreads();

    uint32_t qah[4][4], qal[4][4];
    {
        const float* Qs = (const float*)smu;
#pragma unroll
        for (int ks = 0; ks < 4; ks++) {
            const int j0 = ks * 8 + tm4;
#pragma unroll
            for (int p = 0; p < 4; p++) {
                const int r = w16 + t4 + ((p & 1) ? 8 : 0);
                const int j = j0 + ((p >> 1) ? 4 : 0);
                float v0 = 0.125f * Qs[r * 68 + 2 * j];
                float v1 = 0.125f * Qs[r * 68 + 2 * j + 1];
                float h0 = bf16round(v0), h1 = bf16round(v1);
                qah[ks][p] = pack_bf16(h0, h1);
                qal[ks][p] = pack_bf16(v0 - h0, v1 - h1);
            }
        }
    }
    __syncthreads();   // Q staging done; P area free

    float m0 = -1e30f, m1 = -1e30f, l0 = 0.f, l1 = 0.f;
    float oacc[8][4];
#pragma unroll
    for (int nt = 0; nt < 8; nt++)
#pragma unroll
        for (int r = 0; r < 4; r++) oacc[nt][r] = 0.f;

    for (int kt = 0; kt <= qt; kt++) {
        const int buf = kt & 1;
        asm volatile("cp.async.wait_group 0;\n");
        __syncthreads();
        if (kt < qt) prefetch_kv(buf ^ 1, kt + 1);

        const uint32_t* KbH = smu + OFF_K + buf * 2 * APLANE;
        const uint32_t* KbL = KbH + APLANE;
        const uint32_t* VbH = smu + OFF_VT + buf * 2 * APLANE;
        const uint32_t* VbL = VbH + APLANE;

        // ---- S = (Q*0.125) @ K^T  (3xBF16, m16n8k16, 4 k-steps) ----
        float s[8][4];
#pragma unroll
        for (int nt = 0; nt < 8; nt++)
#pragma unroll
            for (int r = 0; r < 4; r++) s[nt][r] = 0.f;

#pragma unroll
        for (int ks = 0; ks < 4; ks++) {
            const int k0u = ks * 8;
            uint32_t bh[8][2], bl[8][2];
#pragma unroll
            for (int nt = 0; nt < 8; nt++) {
                const int i0 = (nt * 8 + t4) * KSTR + k0u + tm4;
                bh[nt][0] = KbH[i0];     bl[nt][0] = KbL[i0];
                bh[nt][1] = KbH[i0 + 4]; bl[nt][1] = KbL[i0 + 4];
            }
#pragma unroll
            for (int nt = 0; nt < 8; nt++) {
                mma_bf16(s[nt], qal[ks], bh[nt]);
                mma_bf16(s[nt], qah[ks], bl[nt]);
                mma_bf16(s[nt], qah[ks], bh[nt]);
            }
        }

        if (kt == qt) {
#pragma unroll
            for (int nt = 0; nt < 8; nt++) {
                const int c0 = nt * 8 + tm4 * 2;
                const int r0 = w16 + t4;
                if (c0     > r0)     s[nt][0] = -1e30f;
                if (c0 + 1 > r0)     s[nt][1] = -1e30f;
                if (c0     > r0 + 8) s[nt][2] = -1e30f;
                if (c0 + 1 > r0 + 8) s[nt][3] = -1e30f;
            }
        }

        // ---- online softmax (fp32 exact) ----
        float rm0 = -1e30f, rm1 = -1e30f;
#pragma unroll
        for (int nt = 0; nt < 8; nt++) {
            rm0 = fmaxf(rm0, fmaxf(s[nt][0], s[nt][1]));
            rm1 = fmaxf(rm1, fmaxf(s[nt][2], s[nt][3]));
        }
#pragma unroll
        for (int o = 1; o <= 2; o <<= 1) {
            rm0 = fmaxf(rm0, __shfl_xor_sync(0xffffffffu, rm0, o));
            rm1 = fmaxf(rm1, __shfl_xor_sync(0xffffffffu, rm1, o));
        }
        const float nm0 = fmaxf(m0, rm0);
        const float nm1 = fmaxf(m1, rm1);
        const float c0 = expf(m0 - nm0);
        const float c1 = expf(m1 - nm1);
        float rs0 = 0.f, rs1 = 0.f;
#pragma unroll
        for (int nt = 0; nt < 8; nt++) {
            s[nt][0] = expf(s[nt][0] - nm0);
            s[nt][1] = expf(s[nt][1] - nm0);
            s[nt][2] = expf(s[nt][2] - nm1);
            s[nt][3] = expf(s[nt][3] - nm1);
            rs0 += s[nt][0] + s[nt][1];
            rs1 += s[nt][2] + s[nt][3];
        }
#pragma unroll
        for (int o = 1; o <= 2; o <<= 1) {
            rs0 += __shfl_xor_sync(0xffffffffu, rs0, o);
            rs1 += __shfl_xor_sync(0xffffffffu, rs1, o);
        }
        l0 = l0 * c0 + rs0;  m0 = nm0;
        l1 = l1 * c1 + rs1;  m1 = nm1;
#pragma unroll
        for (int nt = 0; nt < 8; nt++) {
            oacc[nt][0] *= c0; oacc[nt][1] *= c0;
            oacc[nt][2] *= c1; oacc[nt][3] *= c1;
        }

        // ---- P split hi/lo, packed STS ----
#pragma unroll
        for (int nt = 0; nt < 8; nt++) {
            const int i0 = (w16 + t4)     * KSTR + nt * 4 + tm4;
            const int i1 = (w16 + t4 + 8) * KSTR + nt * 4 + tm4;
            float h0 = bf16round(s[nt][0]), h1 = bf16round(s[nt][1]);
            float h2 = bf16round(s[nt][2]), h3 = bf16round(s[nt][3]);
            Ph[i0] = pack_bf16(h0, h1);
            Pl[i0] = pack_bf16(s[nt][0] - h0, s[nt][1] - h1);
            Ph[i1] = pack_bf16(h2, h3);
            Pl[i1] = pack_bf16(s[nt][2] - h2, s[nt][3] - h3);
        }
        __syncwarp();

        // ---- O += P @ V^T  (3xBF16: pl*vh + ph*vl + ph*vh) ----
#pragma unroll
        for (int ks = 0; ks < 4; ks++) {
            const int j0 = ks * 8 + tm4;
            const int r0i = (w16 + t4) * KSTR;
            const int r1i = (w16 + t4 + 8) * KSTR;
            uint32_t pah[4], pal[4];
            pah[0] = Ph[r0i + j0];     pal[0] = Pl[r0i + j0];
            pah[1] = Ph[r1i + j0];     pal[1] = Pl[r1i + j0];
            pah[2] = Ph[r0i + j0 + 4]; pal[2] = Pl[r0i + j0 + 4];
            pah[3] = Ph[r1i + j0 + 4]; pal[3] = Pl[r1i + j0 + 4];
#pragma unroll
            for (int nt = 0; nt < 8; nt++) {
                const int i0 = (nt * 8 + t4) * KSTR + ks * 8 + tm4;
                uint32_t vh[2], vl[2];
                vh[0] = VbH[i0];     vl[0] = VbL[i0];
                vh[1] = VbH[i0 + 4]; vl[1] = VbL[i0 + 4];
                mma_bf16(oacc[nt], pal, vh);
                mma_bf16(oacc[nt], pah, vl);
                mma_bf16(oacc[nt], pah, vh);
            }
        }
        __syncwarp();
    }

    // epilogue: normalize, split to bf16 hi/lo ctx planes
    const float i0 = 1.f / l0, i1 = 1.f / l1;
    const size_t r0 = (size_t)(b * SEQ + qt * 64 + w16 + t4) * D_MODEL;
    const size_t r1 = (size_t)(b * SEQ + qt * 64 + w16 + t4 + 8) * D_MODEL;
#pragma unroll
    for (int nt = 0; nt < 8; nt++) {
        const int col = h * HD + nt * 8 + tm4 * 2;
        float o00 = oacc[nt][0] * i0, o01 = oacc[nt][1] * i0;
        float o10 = oacc[nt][2] * i1, o11 = oacc[nt][3] * i1;
        float h00 = bf16round(o00), h01 = bf16round(o01);
        float h10 = bf16round(o10), h11 = bf16round(o11);
        ((uint32_t*)ctxh)[(r0 + col) >> 1] = pack_bf16(h00, h01);
        ((uint32_t*)ctxl)[(r0 + col) >> 1] = pack_bf16(o00 - h00, o01 - h01);
        ((uint32_t*)ctxh)[(r1 + col) >> 1] = pack_bf16(h10, h11);
        ((uint32_t*)ctxl)[(r1 + col) >> 1] = pack_bf16(o10 - h10, o11 - h11);
    }
}

// ---------------------------------------------------------------------------
extern "C" void kernel_launch(void* const* d_in, const int* in_sizes, int n_in,
                              void* d_out, int out_size) {
    const float* x     = (const float*)d_in[0];
    const float* Wqkv  = (const float*)d_in[1];
    const float* qscl  = (const float*)d_in[2];
    const float* kscl  = (const float*)d_in[3];
    const float* Wout  = (const float*)d_in[4];
    float* out = (float*)d_out;

    float* qkv;
    __nv_bfloat16 *xh, *xl, *wqh, *wql, *woh, *wol, *cth, *ctl;
    uint32_t *kph, *kpl, *vth, *vtl;
    cudaGetSymbolAddress((void**)&qkv, g_qkv);
    cudaGetSymbolAddress((void**)&xh,  g_xh);
    cudaGetSymbolAddress((void**)&xl,  g_xl);
    cudaGetSymbolAddress((void**)&wqh, g_wqh);
    cudaGetSymbolAddress((void**)&wql, g_wql);
    cudaGetSymbolAddress((void**)&woh, g_woh);
    cudaGetSymbolAddress((void**)&wol, g_wol);
    cudaGetSymbolAddress((void**)&cth, g_cth);
    cudaGetSymbolAddress((void**)&ctl, g_ctl);
    cudaGetSymbolAddress((void**)&kph, g_kph);
    cudaGetSymbolAddress((void**)&kpl, g_kpl);
    cudaGetSymbolAddress((void**)&vth, g_vth);
    cudaGetSymbolAddress((void**)&vtl, g_vtl);

    cudaFuncSetAttribute(gemm_bf16x3_kernel,
                         cudaFuncAttributeMaxDynamicSharedMemorySize, GEMM_SMEM_BYTES);
    cudaFuncSetAttribute(attn_bf16_kernel,
                         cudaFuncAttributeMaxDynamicSharedMemorySize, ATTN_SMEM_BYTES);

    // 0) splits: x elementwise; weights transpose+split
    {
        int n4x = ROWS * D_MODEL / 4;
        xsplit_kernel<<<(n4x + 255) / 256, 256>>>(x, xh, xl, n4x);
        dim3 gq(QKV_N / 32, D_MODEL / 32);
        trsplit_kernel<<<gq, 256>>>(Wqkv, wqh, wql, D_MODEL, QKV_N);
        dim3 go(D_MODEL / 32, D_MODEL / 32);
        trsplit_kernel<<<go, 256>>>(Wout, woh, wol, D_MODEL, D_MODEL);
    }
    // 1) qkv = x @ W_qkv   (3xBF16)
    {
        dim3 grid(QKV_N / BN, ROWS / BM);
        gemm_bf16x3_kernel<<<grid, 256, GEMM_SMEM_BYTES>>>(
            xh, xl, wqh, wql, qkv, ROWS, QKV_N, D_MODEL);
    }
    // 2) LN (q fp32 in place, k -> bf16 planes); V^T split
    {
        dim3 grid(ROWS, 2);
        ln_kernel<<<grid, 256>>>(qkv, qscl, kscl, kph, kpl);
        dim3 gv(SEQ / 32, HD / 32, BATCH * N_HEADS);
        vtsplit_kernel<<<gv, 256>>>(qkv, vth, vtl);
    }
    // 3) causal flash attention (all-bf16x3) -> bf16 hi/lo ctx planes
    {
        dim3 grid(SEQ / 64, N_HEADS, BATCH);
        attn_bf16_kernel<<<grid, 128, ATTN_SMEM_BYTES>>>(
            qkv, kph, kpl, vth, vtl, cth, ctl);
    }
    // 4) out = ctx @ W_out  (3xBF16)
    {
        dim3 grid(D_MODEL / BN, ROWS / BM);
        gemm_bf16x3_kernel<<<grid, 256, GEMM_SMEM_BYTES>>>(
            cth, ctl, woh, wol, out, ROWS, D_MODEL, D_MODEL);
    }
}